// round 13
// baseline (speedup 1.0000x reference)
#include <cuda_runtime.h>
#include <cuda_bf16.h>
#include <cstdint>

#define NN 32768
#define DD 128
#define DIc 256
#define DSc 16
#define LC 64
#define NCH (NN / LC)
#define EPSF 1e-5f
#define LOG2E 1.4426950408889634f
#define LN2F 0.6931471805599453f

// ---------------- scratch (device globals; no allocation allowed) -------------
__device__ float g_resid[NN * DD];
__device__ __nv_bfloat16 g_rmsb[NN * DD];
__device__ __nv_bfloat16 g_xzb[NN * 2 * DIc];
__device__ __nv_bfloat16 g_xcb[NN * DIc];
__device__ float g_dbc[NN * 64];
__device__ float g_P[NCH * DIc * DSc];
__device__ float g_He[NCH * DIc * DSc];
__device__ float g_Hin[NCH * DIc * DSc];
__device__ __nv_bfloat16 g_yb[NN * DIc];
__device__ float g_x2_unused[1];
__device__ __nv_bfloat16 g_w1b[DD * 512];
__device__ __nv_bfloat16 g_w2b[DIc * 64];
__device__ __nv_bfloat16 g_w3b[DIc * DD];

// ---------------- helpers -----------------------------------------------------
__device__ __forceinline__ float ex2(float x) {
    float y;
    asm("ex2.approx.ftz.f32 %0, %1;" : "=f"(y) : "f"(x));
    return y;
}
__device__ __forceinline__ float lg2(float x) {
    float y;
    asm("lg2.approx.ftz.f32 %0, %1;" : "=f"(y) : "f"(x));
    return y;
}
__device__ __forceinline__ float fexp(float x) { return ex2(x * LOG2E); }
__device__ __forceinline__ float silu_f(float x) { return x / (1.0f + fexp(-x)); }
__device__ __forceinline__ float softplus_fast(float v) {
    float t = ex2(v * LOG2E);
    float r = LN2F * lg2(1.0f + t);
    return v > 20.0f ? v : r;
}
__device__ __forceinline__ void ldsm4(uint32_t& r0, uint32_t& r1, uint32_t& r2, uint32_t& r3,
                                      uint32_t a) {
    asm volatile("ldmatrix.sync.aligned.m8n8.x4.shared.b16 {%0,%1,%2,%3},[%4];"
                 : "=r"(r0), "=r"(r1), "=r"(r2), "=r"(r3)
                 : "r"(a));
}
__device__ __forceinline__ void ldsm4t(uint32_t& r0, uint32_t& r1, uint32_t& r2, uint32_t& r3,
                                       uint32_t a) {
    asm volatile("ldmatrix.sync.aligned.m8n8.x4.trans.shared.b16 {%0,%1,%2,%3},[%4];"
                 : "=r"(r0), "=r"(r1), "=r"(r2), "=r"(r3)
                 : "r"(a));
}
__device__ __forceinline__ void mma_bf16(float* c, const uint32_t* a, const uint32_t* b) {
    asm volatile(
        "mma.sync.aligned.m16n8k16.row.col.f32.bf16.bf16.f32 "
        "{%0,%1,%2,%3},{%4,%5,%6,%7},{%8,%9},{%0,%1,%2,%3};"
        : "+f"(c[0]), "+f"(c[1]), "+f"(c[2]), "+f"(c[3])
        : "r"(a[0]), "r"(a[1]), "r"(a[2]), "r"(a[3]), "r"(b[0]), "r"(b[1]));
}
__device__ __forceinline__ void cpa16(uint32_t s, const void* g) {
    asm volatile("cp.async.cg.shared.global [%0], [%1], 16;" ::"r"(s), "l"(g));
}
__device__ __forceinline__ void cp_commit() { asm volatile("cp.async.commit_group;"); }
template <int NG>
__device__ __forceinline__ void cp_wait() {
    asm volatile("cp.async.wait_group %0;" ::"n"(NG));
}
// r^(s+1) for s=0..15, log-depth (scalar — verified faster than f32x2 pairs on B300)
__device__ __forceinline__ void pow_chain(float r, float* a) {
    a[0] = r;
    a[1] = r * r;
    a[2] = a[1] * r;
    a[3] = a[1] * a[1];
    a[4] = a[3] * r;
    a[5] = a[2] * a[2];
    a[6] = a[5] * r;
    a[7] = a[3] * a[3];
    a[8] = a[7] * r;
    a[9] = a[4] * a[4];
    a[10] = a[9] * r;
    a[11] = a[5] * a[5];
    a[12] = a[11] * r;
    a[13] = a[6] * a[6];
    a[14] = a[13] * r;
    a[15] = a[7] * a[7];
}

// ---------------- kernel 0: convert weights to bf16 (+ pad x_proj) ------------
__global__ void k_wcvt(const float* __restrict__ w1, const float* __restrict__ xw,
                       const float* __restrict__ w3) {
    int idx = blockIdx.x * blockDim.x + threadIdx.x;
    if (idx < DD * 512) {
        g_w1b[idx] = __float2bfloat16(w1[idx]);
    } else if (idx < DD * 512 + DIc * 64) {
        int i = idx - DD * 512;
        int k = i >> 6, j = i & 63;
        g_w2b[i] = __float2bfloat16(j < 40 ? xw[k * 40 + j] : 0.0f);
    } else {
        int i = idx - DD * 512 - DIc * 64;
        g_w3b[i] = __float2bfloat16(w3[i]);
    }
}

// ---------------- kernel 1: pos-encode + gather(perm) + RMSNorm ---------------
__global__ void k_pre(const float* __restrict__ vf, const int* __restrict__ coords,
                      const int* __restrict__ perm, const float* __restrict__ pos_w,
                      const float* __restrict__ pos_b, const float* __restrict__ rms_w) {
    int i = blockIdx.x;
    int d = threadIdx.x;  // 128
    int j = perm[i];
    int cz = coords[j * 4 + 1];
    int cy = coords[j * 4 + 2];
    int cx = coords[j * 4 + 3];
    const float dnm = 1.0f / 43.0f;
    const float t12 = 1.0f / 12.0f;
    float pf[9];
    pf[0] = (float)cz * (1.0f / 16.0f);
    pf[1] = (float)(cy / 12) * dnm;
    pf[2] = (float)(cx / 12) * dnm;
    pf[3] = (float)(cy % 12) * t12;
    pf[4] = (float)(cx % 12) * t12;
    pf[5] = (float)((cy + 6) / 12) * dnm;
    pf[6] = (float)((cx + 6) / 12) * dnm;
    pf[7] = (float)((cy + 6) % 12) * t12;
    pf[8] = (float)((cx + 6) % 12) * t12;
    float pe = pos_b[d];
#pragma unroll
    for (int f = 0; f < 9; f++) pe = fmaf(pf[f], pos_w[f * DD + d], pe);
    float val = vf[(size_t)j * DD + d] + pe;
    g_resid[(size_t)i * DD + d] = val;

    float v2 = val * val;
#pragma unroll
    for (int o = 16; o > 0; o >>= 1) v2 += __shfl_xor_sync(0xffffffffu, v2, o);
    __shared__ float red[4];
    if ((d & 31) == 0) red[d >> 5] = v2;
    __syncthreads();
    float ms = (red[0] + red[1] + red[2] + red[3]) * (1.0f / 128.0f);
    g_rmsb[(size_t)i * DD + d] = __float2bfloat16(val * rsqrtf(ms + EPSF) * rms_w[d]);
}

// ---------------- bf16 TC GEMM, cp.async double-buffered ----------------------
template <int MT, bool OUTB, int Nc, int Kd>
__global__ void bgemm(const __nv_bfloat16* __restrict__ A, const __nv_bfloat16* __restrict__ B,
                      void* __restrict__ Cout) {
    constexpr int BM = MT * 64;
    constexpr int BK = 32;
    constexpr int LDA = 112;
    constexpr int LDB = 144;
    __shared__ __align__(16) unsigned char As[2][BM * LDA];
    __shared__ __align__(16) unsigned char Bs[2][BK * LDB];
    int tid = threadIdx.x;
    int lane = tid & 31;
    int warp = tid >> 5;
    int wr = warp & 3;
    int wc = warp >> 2;
    long row0 = (long)blockIdx.x * BM;
    int col0 = blockIdx.y * 64;

    float acc[MT][4][4];
#pragma unroll
    for (int m = 0; m < MT; m++)
#pragma unroll
        for (int n = 0; n < 4; n++)
#pragma unroll
            for (int r = 0; r < 4; r++) acc[m][n][r] = 0.0f;

    uint32_t asb[2], bsb[2];
    asb[0] = (uint32_t)__cvta_generic_to_shared(&As[0][0]);
    asb[1] = (uint32_t)__cvta_generic_to_shared(&As[1][0]);
    bsb[0] = (uint32_t)__cvta_generic_to_shared(&Bs[0][0]);
    bsb[1] = (uint32_t)__cvta_generic_to_shared(&Bs[1][0]);

    int ar = tid >> 2, ac = tid & 3;
    int br = tid >> 3, bc = tid & 7;

    auto issue = [&](int buf, int k0) {
#pragma unroll
        for (int it = 0; it < MT; it++) {
            int r = ar + it * 64;
            cpa16(asb[buf] + r * LDA + ac * 16, A + (row0 + r) * Kd + k0 + ac * 8);
        }
        cpa16(bsb[buf] + br * LDB + bc * 16, B + (long)(k0 + br) * Nc + col0 + bc * 8);
        cp_commit();
    };

    constexpr int KT = Kd / BK;
    issue(0, 0);
    int buf = 0;

    int a_row_in_tile = lane & 15;
    int a_colh = (lane >> 4) << 3;
    int b_krow = (lane & 7) + (((lane >> 3) & 1) << 3);
    int b_ncol = (lane >> 4) << 3;

    for (int kt = 0; kt < KT; kt++) {
        if (kt + 1 < KT) {
            issue(buf ^ 1, (kt + 1) * BK);
            cp_wait<1>();
        } else {
            cp_wait<0>();
        }
        __syncthreads();
#pragma unroll
        for (int ks = 0; ks < 2; ks++) {
            int kh = ks * 16;
            uint32_t a[MT][4];
#pragma unroll
            for (int mt = 0; mt < MT; mt++) {
                int row = wr * (MT * 16) + mt * 16 + a_row_in_tile;
                ldsm4(a[mt][0], a[mt][1], a[mt][2], a[mt][3],
                      asb[buf] + row * LDA + (kh + a_colh) * 2);
            }
            uint32_t b[4][2];
#pragma unroll
            for (int np = 0; np < 2; np++) {
                int krow = kh + b_krow;
                int ncol = wc * 32 + np * 16 + b_ncol;
                uint32_t r0, r1, r2, r3;
                ldsm4t(r0, r1, r2, r3, bsb[buf] + krow * LDB + ncol * 2);
                b[np * 2][0] = r0;
                b[np * 2][1] = r1;
                b[np * 2 + 1][0] = r2;
                b[np * 2 + 1][1] = r3;
            }
#pragma unroll
            for (int mt = 0; mt < MT; mt++)
#pragma unroll
                for (int nt = 0; nt < 4; nt++) mma_bf16(acc[mt][nt], a[mt], b[nt]);
        }
        __syncthreads();
        buf ^= 1;
    }

    int g = lane >> 2;
    int tg = lane & 3;
#pragma unroll
    for (int mt = 0; mt < MT; mt++) {
#pragma unroll
        for (int nt = 0; nt < 4; nt++) {
            long r0 = row0 + wr * (MT * 16) + mt * 16 + g;
            int c = col0 + wc * 32 + nt * 8 + tg * 2;
            if (OUTB) {
                __nv_bfloat16* C = (__nv_bfloat16*)Cout;
                *(__nv_bfloat162*)(C + r0 * Nc + c) =
                    __float22bfloat162_rn(make_float2(acc[mt][nt][0], acc[mt][nt][1]));
                *(__nv_bfloat162*)(C + (r0 + 8) * Nc + c) =
                    __float22bfloat162_rn(make_float2(acc[mt][nt][2], acc[mt][nt][3]));
            } else {
                float* C = (float*)Cout;
                *(float2*)(C + r0 * Nc + c) = make_float2(acc[mt][nt][0], acc[mt][nt][1]);
                *(float2*)(C + (r0 + 8) * Nc + c) = make_float2(acc[mt][nt][2], acc[mt][nt][3]);
            }
        }
    }
}

// ---------------- kernel 3: causal conv — 2 channels/thread, bf16x2 I/O -------
__global__ void k_conv(const float* __restrict__ conv_w, const float* __restrict__ conv_b) {
    int idx = blockIdx.x * blockDim.x + threadIdx.x;  // (NN/8)*128
    int tb = idx >> 7;
    int cp = idx & 127;
    int c = cp * 2;
    int t0 = tb * 8;
    float4 wA = *(const float4*)(conv_w + c * 4);
    float4 wB = *(const float4*)(conv_w + c * 4 + 4);
    float2 bias = *(const float2*)(conv_b + c);
    float2 v[11];
#pragma unroll
    for (int i = 0; i < 11; i++) {
        int t = t0 - 3 + i;
        if (t >= 0) {
            __nv_bfloat162 h = *(const __nv_bfloat162*)(g_xzb + (size_t)t * 512 + c);
            v[i] = __bfloat1622float2(h);
        } else {
            v[i] = make_float2(0.0f, 0.0f);
        }
    }
#pragma unroll
    for (int j = 0; j < 8; j++) {
        float sa = bias.x, sb = bias.y;
        sa = fmaf(wA.x, v[j].x, sa);
        sb = fmaf(wB.x, v[j].y, sb);
        sa = fmaf(wA.y, v[j + 1].x, sa);
        sb = fmaf(wB.y, v[j + 1].y, sb);
        sa = fmaf(wA.z, v[j + 2].x, sa);
        sb = fmaf(wB.z, v[j + 2].y, sb);
        sa = fmaf(wA.w, v[j + 3].x, sa);
        sb = fmaf(wB.w, v[j + 3].y, sb);
        *(__nv_bfloat162*)(g_xcb + (size_t)(t0 + j) * DIc + c) =
            __float22bfloat162_rn(make_float2(silu_f(sa), silu_f(sb)));
    }
}

// ---------------- kernel 7: scan pass 1 (inline dt; scalar; LC=64) ------------
__global__ void k_scan1(const float* __restrict__ A_log, const float* __restrict__ dtw,
                        const float* __restrict__ dtb) {
    int chunk = blockIdx.x;
    int c = threadIdx.x;
    __shared__ float U[LC][8];
    __shared__ float Bsh[LC][16];
    int t0 = chunk * LC;
    {
        int tid = threadIdx.x;
        if (tid < LC * 2) {
            int row = tid >> 1, q = tid & 1;
            *(float4*)&U[row][q * 4] = *(const float4*)(g_dbc + (size_t)(t0 + row) * 64 + q * 4);
        }
        int r2 = tid >> 2, q2 = tid & 3;
        *(float4*)&Bsh[r2][q2 * 4] = *(const float4*)(g_dbc + (size_t)(t0 + r2) * 64 + 8 + q2 * 4);
    }
    __syncthreads();
    float w8[8];
#pragma unroll
    for (int k = 0; k < 8; k++) w8[k] = dtw[k * DIc + c];
    float b0 = dtb[c];
    float A2[DSc];
#pragma unroll
    for (int s = 0; s < DSc; s++) A2[s] = -__expf(A_log[c * DSc + s]) * LOG2E;
    float base = A2[0];
    bool structured = true;
#pragma unroll
    for (int s = 0; s < DSc; s++) {
        float e = base * (float)(s + 1);
        structured = structured && (fabsf(A2[s] - e) <= 1e-5f * fabsf(e) + 1e-30f);
    }
    float h[DSc];
#pragma unroll
    for (int s = 0; s < DSc; s++) h[s] = 0.0f;
    float sdt = 0.0f;
    size_t o = ((size_t)chunk * DIc + c) * DSc;
    if (structured) {
#pragma unroll 2
        for (int t = 0; t < LC; t++) {
            float dot = b0;
#pragma unroll
            for (int k = 0; k < 8; k++) dot = fmaf(w8[k], U[t][k], dot);
            float d = softplus_fast(dot);
            float x = __bfloat162float(g_xcb[(size_t)(t0 + t) * DIc + c]);
            float dx = d * x;
            sdt += d;
            float a[DSc];
            pow_chain(ex2(d * base), a);
#pragma unroll
            for (int s = 0; s < DSc; s++) h[s] = fmaf(a[s], h[s], dx * Bsh[t][s]);
        }
    } else {
#pragma unroll 2
        for (int t = 0; t < LC; t++) {
            float dot = b0;
#pragma unroll
            for (int k = 0; k < 8; k++) dot = fmaf(w8[k], U[t][k], dot);
            float d = softplus_fast(dot);
            float x = __bfloat162float(g_xcb[(size_t)(t0 + t) * DIc + c]);
            float dx = d * x;
            sdt += d;
#pragma unroll
            for (int s = 0; s < DSc; s++) {
                float a = ex2(d * A2[s]);
                h[s] = fmaf(a, h[s], dx * Bsh[t][s]);
            }
        }
    }
#pragma unroll
    for (int s = 0; s < DSc; s++) {
        g_He[o + s] = h[s];
        g_P[o + s] = ex2(sdt * A2[s]);
    }
}

// ---------------- kernel 8: cross-chunk combine -------------------------------
__global__ void k_combine() {
    int idx = blockIdx.x * blockDim.x + threadIdx.x;
    float h = 0.0f;
    for (int k = 0; k < NCH; k++) {
        size_t o = (size_t)k * DIc * DSc + idx;
        g_Hin[o] = h;
        h = fmaf(g_P[o], h, g_He[o]);
    }
}

// ---------------- kernel 9: scan pass 2 (inline dt; scalar; LC=64) ------------
__global__ void k_scan2(const float* __restrict__ A_log, const float* __restrict__ dtw,
                        const float* __restrict__ dtb, const float* __restrict__ Dskip) {
    int chunk = blockIdx.x;
    int c = threadIdx.x;
    __shared__ float U[LC][8];
    __shared__ float Bsh[LC][16];
    __shared__ float Csh[LC][16];
    int t0 = chunk * LC;
    {
        int tid = threadIdx.x;
        if (tid < LC * 2) {
            int row = tid >> 1, q = tid & 1;
            *(float4*)&U[row][q * 4] = *(const float4*)(g_dbc + (size_t)(t0 + row) * 64 + q * 4);
        }
        int r2 = tid >> 2, q2 = tid & 3;
        *(float4*)&Bsh[r2][q2 * 4] = *(const float4*)(g_dbc + (size_t)(t0 + r2) * 64 + 8 + q2 * 4);
        *(float4*)&Csh[r2][q2 * 4] =
            *(const float4*)(g_dbc + (size_t)(t0 + r2) * 64 + 24 + q2 * 4);
    }
    __syncthreads();
    float w8[8];
#pragma unroll
    for (int k = 0; k < 8; k++) w8[k] = dtw[k * DIc + c];
    float b0 = dtb[c];
    float A2[DSc];
#pragma unroll
    for (int s = 0; s < DSc; s++) A2[s] = -__expf(A_log[c * DSc + s]) * LOG2E;
    float base = A2[0];
    bool structured = true;
#pragma unroll
    for (int s = 0; s < DSc; s++) {
        float e = base * (float)(s + 1);
        structured = structured && (fabsf(A2[s] - e) <= 1e-5f * fabsf(e) + 1e-30f);
    }
    float h[DSc];
    size_t oh = ((size_t)chunk * DIc + c) * DSc;
#pragma unroll
    for (int s = 0; s < DSc; s++) h[s] = g_Hin[oh + s];
    float dsk = Dskip[c];
    if (structured) {
#pragma unroll 2
        for (int t = 0; t < LC; t++) {
            float dot = b0;
#pragma unroll
            for (int k = 0; k < 8; k++) dot = fmaf(w8[k], U[t][k], dot);
            float d = softplus_fast(dot);
            float x = __bfloat162float(g_xcb[(size_t)(t0 + t) * DIc + c]);
            float z = __bfloat162float(g_xzb[(size_t)(t0 + t) * 512 + DIc + c]);
            float dx = d * x;
            float a[DSc];
            pow_chain(ex2(d * base), a);
            float acc = 0.0f;
#pragma unroll
            for (int s = 0; s < DSc; s++) {
                h[s] = fmaf(a[s], h[s], dx * Bsh[t][s]);
                acc = fmaf(h[s], Csh[t][s], acc);
            }
            acc = fmaf(dsk, x, acc);
            g_yb[(size_t)(t0 + t) * DIc + c] = __float2bfloat16(acc * silu_f(z));
        }
    } else {
#pragma unroll 2
        for (int t = 0; t < LC; t++) {
            float dot = b0;
#pragma unroll
            for (int k = 0; k < 8; k++) dot = fmaf(w8[k], U[t][k], dot);
            float d = softplus_fast(dot);
            float x = __bfloat162float(g_xcb[(size_t)(t0 + t) * DIc + c]);
            float z = __bfloat162float(g_xzb[(size_t)(t0 + t) * 512 + DIc + c]);
            float dx = d * x;
            float acc = 0.0f;
#pragma unroll
            for (int s = 0; s < DSc; s++) {
                float a = ex2(d * A2[s]);
                h[s] = fmaf(a, h[s], dx * Bsh[t][s]);
                acc = fmaf(h[s], Csh[t][s], acc);
            }
            acc = fmaf(dsk, x, acc);
            g_yb[(size_t)(t0 + t) * DIc + c] = __float2bfloat16(acc * silu_f(z));
        }
    }
}

// ---------------- kernel 10: fused out_proj + residual + LN + scatter ---------
__global__ void k_outln(const __nv_bfloat16* __restrict__ A, const __nv_bfloat16* __restrict__ B,
                        const float* __restrict__ resid, const int* __restrict__ perm,
                        const float* __restrict__ ln_w, const float* __restrict__ ln_b,
                        float* __restrict__ out) {
    constexpr int BK = 32, Kd = 256, Nc = 128;
    constexpr int LDA = 112;
    constexpr int LDB = 272;
    __shared__ __align__(16) unsigned char As[2][64 * LDA];
    __shared__ __align__(16) unsigned char Bs[2][BK * LDB];
    __shared__ float redA[64][2], redB[64][2];
    int tid = threadIdx.x;
    int lane = tid & 31;
    int warp = tid >> 5;
    int wr = warp & 3;
    int wc = warp >> 2;
    long row0 = (long)blockIdx.x * 64;

    float acc[8][4];
#pragma unroll
    for (int n = 0; n < 8; n++)
#pragma unroll
        for (int r = 0; r < 4; r++) acc[n][r] = 0.0f;

    uint32_t asb[2], bsb[2];
    asb[0] = (uint32_t)__cvta_generic_to_shared(&As[0][0]);
    asb[1] = (uint32_t)__cvta_generic_to_shared(&As[1][0]);
    bsb[0] = (uint32_t)__cvta_generic_to_shared(&Bs[0][0]);
    bsb[1] = (uint32_t)__cvta_generic_to_shared(&Bs[1][0]);

    int ar = tid >> 2, ac = tid & 3;
    int br = tid >> 3, bc = tid & 7;

    auto issue = [&](int buf, int k0) {
        cpa16(asb[buf] + ar * LDA + ac * 16, A + (row0 + ar) * Kd + k0 + ac * 8);
        cpa16(bsb[buf] + br * LDB + bc * 16, B + (long)(k0 + br) * Nc + bc * 8);
        cpa16(bsb[buf] + br * LDB + 128 + bc * 16, B + (long)(k0 + br) * Nc + 64 + bc * 8);
        cp_commit();
    };

    issue(0, 0);
    int buf = 0;
    int a_row_in_tile = lane & 15;
    int a_colh = (lane >> 4) << 3;
    int b_krow = (lane & 7) + (((lane >> 3) & 1) << 3);
    int b_ncol = (lane >> 4) << 3;

    constexpr int KT = Kd / BK;
    for (int kt = 0; kt < KT; kt++) {
        if (kt + 1 < KT) {
            issue(buf ^ 1, (kt + 1) * BK);
            cp_wait<1>();
        } else {
            cp_wait<0>();
        }
        __syncthreads();
#pragma unroll
        for (int ks = 0; ks < 2; ks++) {
            int kh = ks * 16;
            uint32_t a[4];
            {
                int row = wr * 16 + a_row_in_tile;
                ldsm4(a[0], a[1], a[2], a[3], asb[buf] + row * LDA + (kh + a_colh) * 2);
            }
            uint32_t b[8][2];
#pragma unroll
            for (int np = 0; np < 4; np++) {
                int krow = kh + b_krow;
                int ncol = wc * 64 + np * 16 + b_ncol;
                uint32_t r0, r1, r2, r3;
                ldsm4t(r0, r1, r2, r3, bsb[buf] + krow * LDB + ncol * 2);
                b[np * 2][0] = r0;
                b[np * 2][1] = r1;
                b[np * 2 + 1][0] = r2;
                b[np * 2 + 1][1] = r3;
            }
#pragma unroll
            for (int nt = 0; nt < 8; nt++) mma_bf16(acc[nt], a, b[nt]);
        }
        __syncthreads();
        buf ^= 1;
    }

    int g = lane >> 2;
    int tg = lane & 3;
    int rA = wr * 16 + g;
    int rB = rA + 8;
    float va[16], vb[16];
    float s1a = 0.f, s2a = 0.f, s1b = 0.f, s2b = 0.f;
#pragma unroll
    for (int nt = 0; nt < 8; nt++) {
        int cc = wc * 64 + nt * 8 + tg * 2;
        float2 sa = *(const float2*)(resid + (row0 + rA) * Nc + cc);
        float2 sb = *(const float2*)(resid + (row0 + rB) * Nc + cc);
        float x0 = acc[nt][0] + sa.x, x1 = acc[nt][1] + sa.y;
        float x2 = acc[nt][2] + sb.x, x3 = acc[nt][3] + sb.y;
        va[nt * 2] = x0; va[nt * 2 + 1] = x1;
        vb[nt * 2] = x2; vb[nt * 2 + 1] = x3;
        s1a += x0 + x1; s2a += x0 * x0 + x1 * x1;
        s1b += x2 + x3; s2b += x2 * x2 + x3 * x3;
    }
#pragma unroll
    for (int o = 1; o <= 2; o <<= 1) {
        s1a += __shfl_xor_sync(0xffffffffu, s1a, o);
        s2a += __shfl_xor_sync(0xffffffffu, s2a, o);
        s1b += __shfl_xor_sync(0xffffffffu, s1b, o);
        s2b += __shfl_xor_sync(0xffffffffu, s2b, o);
    }
    if (tg == 0) {
        redA[rA][wc] = s1a; redB[rA][wc] = s2a;
        redA[rB][wc] = s1b; redB[rB][wc] = s2b;
    }
    __syncthreads();
    float muA = (redA[rA][0] + redA[rA][1]) * (1.0f / 128.0f);
    float e2A = (redB[rA][0] + redB[rA][1]) * (1.0f / 128.0f);
    float muB = (redA[rB][0] + redA[rB][1]) * (1.0f / 128.0f);
    float e2B = (redB[rB][0] + redB[rB][1]) * (1.0f / 128.0f);
    float rsA = rsqrtf(e2A - muA * muA + EPSF);
    float rsB = rsqrtf(e2B - muB * muB + EPSF);
    int prA = perm[row0 + rA];
    int prB = perm[row0 + rB];
#pragma unroll
    for (int nt = 0; nt < 8; nt++) {
        int cc = wc * 64 + nt * 8 + tg * 2;
        float2 w = *(const float2*)(ln_w + cc);
        float2 bb = *(const float2*)(ln_b + cc);
        float2 oa, ob;
        oa.x = (va[nt * 2] - muA) * rsA * w.x + bb.x;
        oa.y = (va[nt * 2 + 1] - muA) * rsA * w.y + bb.y;
        ob.x = (vb[nt * 2] - muB) * rsB * w.x + bb.x;
        ob.y = (vb[nt * 2 + 1] - muB) * rsB * w.y + bb.y;
        *(float2*)(out + (size_t)prA * Nc + cc) = oa;
        *(float2*)(out + (size_t)prB * Nc + cc) = ob;
    }
}

// ---------------- host ---------------------------------------------------------
extern "C" void kernel_launch(void* const* d_in, const int* in_sizes, int n_in,
                              void* d_out, int out_size) {
    const float *vf, *pos_w, *pos_b, *rms_w, *in_proj_w, *conv_w, *conv_b, *x_proj_w;
    const float *dt_w, *dt_b, *A_log, *Dskip, *out_proj_w, *ln_w, *ln_b;
    const int *coords, *perm, *inv_perm;

    if (in_sizes[1] == NN * 4) {
        vf = (const float*)d_in[0];
        coords = (const int*)d_in[1];
        perm = (const int*)d_in[2];
        inv_perm = (const int*)d_in[3];
        pos_w = (const float*)d_in[4];
        pos_b = (const float*)d_in[5];
        rms_w = (const float*)d_in[6];
        in_proj_w = (const float*)d_in[7];
        conv_w = (const float*)d_in[8];
        conv_b = (const float*)d_in[9];
        x_proj_w = (const float*)d_in[10];
        dt_w = (const float*)d_in[11];
        dt_b = (const float*)d_in[12];
        A_log = (const float*)d_in[13];
        Dskip = (const float*)d_in[14];
        out_proj_w = (const float*)d_in[15];
        ln_w = (const float*)d_in[16];
        ln_b = (const float*)d_in[17];
    } else {
        vf = (const float*)d_in[0];
        pos_w = (const float*)d_in[1];
        pos_b = (const float*)d_in[2];
        rms_w = (const float*)d_in[3];
        in_proj_w = (const float*)d_in[4];
        conv_w = (const float*)d_in[5];
        conv_b = (const float*)d_in[6];
        x_proj_w = (const float*)d_in[7];
        dt_w = (const float*)d_in[8];
        dt_b = (const float*)d_in[9];
        A_log = (const float*)d_in[10];
        Dskip = (const float*)d_in[11];
        out_proj_w = (const float*)d_in[12];
        ln_w = (const float*)d_in[13];
        ln_b = (const float*)d_in[14];
        coords = (const int*)d_in[15];
        perm = (const int*)d_in[16];
        inv_perm = (const int*)d_in[17];
    }
    (void)inv_perm;

    void *p_rmsb, *p_xzb, *p_xcb, *p_dbc, *p_yb, *p_resid, *p_w1b, *p_w2b, *p_w3b;
    cudaGetSymbolAddress(&p_rmsb, g_rmsb);
    cudaGetSymbolAddress(&p_xzb, g_xzb);
    cudaGetSymbolAddress(&p_xcb, g_xcb);
    cudaGetSymbolAddress(&p_dbc, g_dbc);
    cudaGetSymbolAddress(&p_yb, g_yb);
    cudaGetSymbolAddress(&p_resid, g_resid);
    cudaGetSymbolAddress(&p_w1b, g_w1b);
    cudaGetSymbolAddress(&p_w2b, g_w2b);
    cudaGetSymbolAddress(&p_w3b, g_w3b);

    k_wcvt<<<448, 256>>>(in_proj_w, x_proj_w, out_proj_w);
    k_pre<<<NN, 128>>>(vf, coords, perm, pos_w, pos_b, rms_w);
    bgemm<2, true, 512, 128><<<dim3(NN / 128, 512 / 64), 256>>>(
        (const __nv_bfloat16*)p_rmsb, (const __nv_bfloat16*)p_w1b, p_xzb);
    k_conv<<<(NN / 16), 256>>>(conv_w, conv_b);
    bgemm<1, false, 64, 256><<<dim3(NN / 64, 1), 256>>>(
        (const __nv_bfloat16*)p_xcb, (const __nv_bfloat16*)p_w2b, p_dbc);
    k_scan1<<<NCH, 256>>>(A_log, dt_w, dt_b);
    k_combine<<<DIc * DSc / 256, 256>>>();
    k_scan2<<<NCH, 256>>>(A_log, dt_w, dt_b, Dskip);
    k_outln<<<NN / 64, 256>>>((const __nv_bfloat16*)p_yb, (const __nv_bfloat16*)p_w3b,
                              (const float*)p_resid, perm, ln_w, ln_b, (float*)d_out);
    (void)n_in;
    (void)out_size;
    (void)in_sizes;
}

// round 14
// speedup vs baseline: 1.4143x; 1.4143x over previous
#include <cuda_runtime.h>
#include <cuda_bf16.h>
#include <cstdint>

#define NN 32768
#define DD 128
#define DIc 256
#define DSc 16
#define LC 128
#define NCH (NN / LC)
#define EPSF 1e-5f
#define LOG2E 1.4426950408889634f
#define LN2F 0.6931471805599453f

// ---------------- scratch (device globals; no allocation allowed) -------------
__device__ float g_resid[NN * DD];
__device__ __nv_bfloat16 g_rmsb[NN * DD];
__device__ __nv_bfloat16 g_xzb[NN * 2 * DIc];
__device__ __nv_bfloat16 g_xcb[NN * DIc];
__device__ float g_dbc[NN * 64];
__device__ float g_P[NCH * DIc * DSc];
__device__ float g_He[NCH * DIc * DSc];
__device__ float g_Hin[NCH * DIc * DSc];
__device__ __nv_bfloat16 g_yb[NN * DIc];
__device__ __nv_bfloat16 g_w1b[DD * 512];
__device__ __nv_bfloat16 g_w2b[DIc * 64];
__device__ __nv_bfloat16 g_w3b[DIc * DD];

// ---------------- helpers -----------------------------------------------------
__device__ __forceinline__ float ex2(float x) {
    float y;
    asm("ex2.approx.ftz.f32 %0, %1;" : "=f"(y) : "f"(x));
    return y;
}
__device__ __forceinline__ float lg2(float x) {
    float y;
    asm("lg2.approx.ftz.f32 %0, %1;" : "=f"(y) : "f"(x));
    return y;
}
__device__ __forceinline__ float fexp(float x) { return ex2(x * LOG2E); }
__device__ __forceinline__ float silu_f(float x) { return x / (1.0f + fexp(-x)); }
__device__ __forceinline__ float softplus_fast(float v) {
    float t = ex2(v * LOG2E);
    float r = LN2F * lg2(1.0f + t);
    return v > 20.0f ? v : r;
}
__device__ __forceinline__ void ldsm4(uint32_t& r0, uint32_t& r1, uint32_t& r2, uint32_t& r3,
                                      uint32_t a) {
    asm volatile("ldmatrix.sync.aligned.m8n8.x4.shared.b16 {%0,%1,%2,%3},[%4];"
                 : "=r"(r0), "=r"(r1), "=r"(r2), "=r"(r3)
                 : "r"(a));
}
__device__ __forceinline__ void ldsm4t(uint32_t& r0, uint32_t& r1, uint32_t& r2, uint32_t& r3,
                                       uint32_t a) {
    asm volatile("ldmatrix.sync.aligned.m8n8.x4.trans.shared.b16 {%0,%1,%2,%3},[%4];"
                 : "=r"(r0), "=r"(r1), "=r"(r2), "=r"(r3)
                 : "r"(a));
}
__device__ __forceinline__ void mma_bf16(float* c, const uint32_t* a, const uint32_t* b) {
    asm volatile(
        "mma.sync.aligned.m16n8k16.row.col.f32.bf16.bf16.f32 "
        "{%0,%1,%2,%3},{%4,%5,%6,%7},{%8,%9},{%0,%1,%2,%3};"
        : "+f"(c[0]), "+f"(c[1]), "+f"(c[2]), "+f"(c[3])
        : "r"(a[0]), "r"(a[1]), "r"(a[2]), "r"(a[3]), "r"(b[0]), "r"(b[1]));
}
__device__ __forceinline__ void cpa16(uint32_t s, const void* g) {
    asm volatile("cp.async.cg.shared.global [%0], [%1], 16;" ::"r"(s), "l"(g));
}
__device__ __forceinline__ void cp_commit() { asm volatile("cp.async.commit_group;"); }
template <int NG>
__device__ __forceinline__ void cp_wait() {
    asm volatile("cp.async.wait_group %0;" ::"n"(NG));
}
// r^(s+1) for s=0..15, log-depth (scalar — verified faster than f32x2 pairs on B300)
__device__ __forceinline__ void pow_chain(float r, float* a) {
    a[0] = r;
    a[1] = r * r;
    a[2] = a[1] * r;
    a[3] = a[1] * a[1];
    a[4] = a[3] * r;
    a[5] = a[2] * a[2];
    a[6] = a[5] * r;
    a[7] = a[3] * a[3];
    a[8] = a[7] * r;
    a[9] = a[4] * a[4];
    a[10] = a[9] * r;
    a[11] = a[5] * a[5];
    a[12] = a[11] * r;
    a[13] = a[6] * a[6];
    a[14] = a[13] * r;
    a[15] = a[7] * a[7];
}

// ---------------- kernel 0: convert weights to bf16 (+ pad x_proj) ------------
__global__ void k_wcvt(const float* __restrict__ w1, const float* __restrict__ xw,
                       const float* __restrict__ w3) {
    int idx = blockIdx.x * blockDim.x + threadIdx.x;
    if (idx < DD * 512) {
        g_w1b[idx] = __float2bfloat16(w1[idx]);
    } else if (idx < DD * 512 + DIc * 64) {
        int i = idx - DD * 512;
        int k = i >> 6, j = i & 63;
        g_w2b[i] = __float2bfloat16(j < 40 ? xw[k * 40 + j] : 0.0f);
    } else {
        int i = idx - DD * 512 - DIc * 64;
        g_w3b[i] = __float2bfloat16(w3[i]);
    }
}

// ---------------- kernel 1: pos-encode + gather(perm) + RMSNorm ---------------
__global__ void k_pre(const float* __restrict__ vf, const int* __restrict__ coords,
                      const int* __restrict__ perm, const float* __restrict__ pos_w,
                      const float* __restrict__ pos_b, const float* __restrict__ rms_w) {
    int i = blockIdx.x;
    int d = threadIdx.x;  // 128
    int j = perm[i];
    int cz = coords[j * 4 + 1];
    int cy = coords[j * 4 + 2];
    int cx = coords[j * 4 + 3];
    const float dnm = 1.0f / 43.0f;
    const float t12 = 1.0f / 12.0f;
    float pf[9];
    pf[0] = (float)cz * (1.0f / 16.0f);
    pf[1] = (float)(cy / 12) * dnm;
    pf[2] = (float)(cx / 12) * dnm;
    pf[3] = (float)(cy % 12) * t12;
    pf[4] = (float)(cx % 12) * t12;
    pf[5] = (float)((cy + 6) / 12) * dnm;
    pf[6] = (float)((cx + 6) / 12) * dnm;
    pf[7] = (float)((cy + 6) % 12) * t12;
    pf[8] = (float)((cx + 6) % 12) * t12;
    float pe = pos_b[d];
#pragma unroll
    for (int f = 0; f < 9; f++) pe = fmaf(pf[f], pos_w[f * DD + d], pe);
    float val = vf[(size_t)j * DD + d] + pe;
    g_resid[(size_t)i * DD + d] = val;

    float v2 = val * val;
#pragma unroll
    for (int o = 16; o > 0; o >>= 1) v2 += __shfl_xor_sync(0xffffffffu, v2, o);
    __shared__ float red[4];
    if ((d & 31) == 0) red[d >> 5] = v2;
    __syncthreads();
    float ms = (red[0] + red[1] + red[2] + red[3]) * (1.0f / 128.0f);
    g_rmsb[(size_t)i * DD + d] = __float2bfloat16(val * rsqrtf(ms + EPSF) * rms_w[d]);
}

// ---------------- bf16 TC GEMM, cp.async double-buffered ----------------------
template <int MT, bool OUTB, int Nc, int Kd>
__global__ void bgemm(const __nv_bfloat16* __restrict__ A, const __nv_bfloat16* __restrict__ B,
                      void* __restrict__ Cout) {
    constexpr int BM = MT * 64;
    constexpr int BK = 32;
    constexpr int LDA = 112;
    constexpr int LDB = 144;
    __shared__ __align__(16) unsigned char As[2][BM * LDA];
    __shared__ __align__(16) unsigned char Bs[2][BK * LDB];
    int tid = threadIdx.x;
    int lane = tid & 31;
    int warp = tid >> 5;
    int wr = warp & 3;
    int wc = warp >> 2;
    long row0 = (long)blockIdx.x * BM;
    int col0 = blockIdx.y * 64;

    float acc[MT][4][4];
#pragma unroll
    for (int m = 0; m < MT; m++)
#pragma unroll
        for (int n = 0; n < 4; n++)
#pragma unroll
            for (int r = 0; r < 4; r++) acc[m][n][r] = 0.0f;

    uint32_t asb[2], bsb[2];
    asb[0] = (uint32_t)__cvta_generic_to_shared(&As[0][0]);
    asb[1] = (uint32_t)__cvta_generic_to_shared(&As[1][0]);
    bsb[0] = (uint32_t)__cvta_generic_to_shared(&Bs[0][0]);
    bsb[1] = (uint32_t)__cvta_generic_to_shared(&Bs[1][0]);

    int ar = tid >> 2, ac = tid & 3;
    int br = tid >> 3, bc = tid & 7;

    auto issue = [&](int buf, int k0) {
#pragma unroll
        for (int it = 0; it < MT; it++) {
            int r = ar + it * 64;
            cpa16(asb[buf] + r * LDA + ac * 16, A + (row0 + r) * Kd + k0 + ac * 8);
        }
        cpa16(bsb[buf] + br * LDB + bc * 16, B + (long)(k0 + br) * Nc + col0 + bc * 8);
        cp_commit();
    };

    constexpr int KT = Kd / BK;
    issue(0, 0);
    int buf = 0;

    int a_row_in_tile = lane & 15;
    int a_colh = (lane >> 4) << 3;
    int b_krow = (lane & 7) + (((lane >> 3) & 1) << 3);
    int b_ncol = (lane >> 4) << 3;

    for (int kt = 0; kt < KT; kt++) {
        if (kt + 1 < KT) {
            issue(buf ^ 1, (kt + 1) * BK);
            cp_wait<1>();
        } else {
            cp_wait<0>();
        }
        __syncthreads();
#pragma unroll
        for (int ks = 0; ks < 2; ks++) {
            int kh = ks * 16;
            uint32_t a[MT][4];
#pragma unroll
            for (int mt = 0; mt < MT; mt++) {
                int row = wr * (MT * 16) + mt * 16 + a_row_in_tile;
                ldsm4(a[mt][0], a[mt][1], a[mt][2], a[mt][3],
                      asb[buf] + row * LDA + (kh + a_colh) * 2);
            }
            uint32_t b[4][2];
#pragma unroll
            for (int np = 0; np < 2; np++) {
                int krow = kh + b_krow;
                int ncol = wc * 32 + np * 16 + b_ncol;
                uint32_t r0, r1, r2, r3;
                ldsm4t(r0, r1, r2, r3, bsb[buf] + krow * LDB + ncol * 2);
                b[np * 2][0] = r0;
                b[np * 2][1] = r1;
                b[np * 2 + 1][0] = r2;
                b[np * 2 + 1][1] = r3;
            }
#pragma unroll
            for (int mt = 0; mt < MT; mt++)
#pragma unroll
                for (int nt = 0; nt < 4; nt++) mma_bf16(acc[mt][nt], a[mt], b[nt]);
        }
        __syncthreads();
        buf ^= 1;
    }

    int g = lane >> 2;
    int tg = lane & 3;
#pragma unroll
    for (int mt = 0; mt < MT; mt++) {
#pragma unroll
        for (int nt = 0; nt < 4; nt++) {
            long r0 = row0 + wr * (MT * 16) + mt * 16 + g;
            int c = col0 + wc * 32 + nt * 8 + tg * 2;
            if (OUTB) {
                __nv_bfloat16* C = (__nv_bfloat16*)Cout;
                *(__nv_bfloat162*)(C + r0 * Nc + c) =
                    __float22bfloat162_rn(make_float2(acc[mt][nt][0], acc[mt][nt][1]));
                *(__nv_bfloat162*)(C + (r0 + 8) * Nc + c) =
                    __float22bfloat162_rn(make_float2(acc[mt][nt][2], acc[mt][nt][3]));
            } else {
                float* C = (float*)Cout;
                *(float2*)(C + r0 * Nc + c) = make_float2(acc[mt][nt][0], acc[mt][nt][1]);
                *(float2*)(C + (r0 + 8) * Nc + c) = make_float2(acc[mt][nt][2], acc[mt][nt][3]);
            }
        }
    }
}

// ---------------- kernel 3: causal conv — 2 channels/thread, bf16x2 I/O -------
__global__ void k_conv(const float* __restrict__ conv_w, const float* __restrict__ conv_b) {
    int idx = blockIdx.x * blockDim.x + threadIdx.x;  // (NN/8)*128
    int tb = idx >> 7;
    int cp = idx & 127;
    int c = cp * 2;
    int t0 = tb * 8;
    float4 wA = *(const float4*)(conv_w + c * 4);
    float4 wB = *(const float4*)(conv_w + c * 4 + 4);
    float2 bias = *(const float2*)(conv_b + c);
    float2 v[11];
#pragma unroll
    for (int i = 0; i < 11; i++) {
        int t = t0 - 3 + i;
        if (t >= 0) {
            __nv_bfloat162 h = *(const __nv_bfloat162*)(g_xzb + (size_t)t * 512 + c);
            v[i] = __bfloat1622float2(h);
        } else {
            v[i] = make_float2(0.0f, 0.0f);
        }
    }
#pragma unroll
    for (int j = 0; j < 8; j++) {
        float sa = bias.x, sb = bias.y;
        sa = fmaf(wA.x, v[j].x, sa);
        sb = fmaf(wB.x, v[j].y, sb);
        sa = fmaf(wA.y, v[j + 1].x, sa);
        sb = fmaf(wB.y, v[j + 1].y, sb);
        sa = fmaf(wA.z, v[j + 2].x, sa);
        sb = fmaf(wB.z, v[j + 2].y, sb);
        sa = fmaf(wA.w, v[j + 3].x, sa);
        sb = fmaf(wB.w, v[j + 3].y, sb);
        *(__nv_bfloat162*)(g_xcb + (size_t)(t0 + j) * DIc + c) =
            __float22bfloat162_rn(make_float2(silu_f(sa), silu_f(sb)));
    }
}

// ---------------- kernel 7: scan pass 1 (inline dt; scalar; LC=128) -----------
__global__ void k_scan1(const float* __restrict__ A_log, const float* __restrict__ dtw,
                        const float* __restrict__ dtb) {
    int chunk = blockIdx.x;
    int c = threadIdx.x;
    __shared__ float U[LC][8];
    __shared__ float Bsh[LC][16];
    int t0 = chunk * LC;
    {
        int row = threadIdx.x >> 1, q = threadIdx.x & 1;
        *(float4*)&U[row][q * 4] = *(const float4*)(g_dbc + (size_t)(t0 + row) * 64 + q * 4);
#pragma unroll
        for (int it = 0; it < 2; it++) {
            int v = threadIdx.x + it * 256;
            int r2 = v >> 2, q2 = v & 3;
            *(float4*)&Bsh[r2][q2 * 4] =
                *(const float4*)(g_dbc + (size_t)(t0 + r2) * 64 + 8 + q2 * 4);
        }
    }
    __syncthreads();
    float w8[8];
#pragma unroll
    for (int k = 0; k < 8; k++) w8[k] = dtw[k * DIc + c];
    float b0 = dtb[c];
    float A2[DSc];
#pragma unroll
    for (int s = 0; s < DSc; s++) A2[s] = -__expf(A_log[c * DSc + s]) * LOG2E;
    float base = A2[0];
    bool structured = true;
#pragma unroll
    for (int s = 0; s < DSc; s++) {
        float e = base * (float)(s + 1);
        structured = structured && (fabsf(A2[s] - e) <= 1e-5f * fabsf(e) + 1e-30f);
    }
    float h[DSc];
#pragma unroll
    for (int s = 0; s < DSc; s++) h[s] = 0.0f;
    float sdt = 0.0f;
    if (structured) {
#pragma unroll 2
        for (int t = 0; t < LC; t++) {
            float dot = b0;
#pragma unroll
            for (int k = 0; k < 8; k++) dot = fmaf(w8[k], U[t][k], dot);
            float d = softplus_fast(dot);
            float x = __bfloat162float(g_xcb[(size_t)(t0 + t) * DIc + c]);
            float dx = d * x;
            sdt += d;
            float a[DSc];
            pow_chain(ex2(d * base), a);
#pragma unroll
            for (int s = 0; s < DSc; s++) h[s] = fmaf(a[s], h[s], dx * Bsh[t][s]);
        }
    } else {
#pragma unroll 2
        for (int t = 0; t < LC; t++) {
            float dot = b0;
#pragma unroll
            for (int k = 0; k < 8; k++) dot = fmaf(w8[k], U[t][k], dot);
            float d = softplus_fast(dot);
            float x = __bfloat162float(g_xcb[(size_t)(t0 + t) * DIc + c]);
            float dx = d * x;
            sdt += d;
#pragma unroll
            for (int s = 0; s < DSc; s++) {
                float a = ex2(d * A2[s]);
                h[s] = fmaf(a, h[s], dx * Bsh[t][s]);
            }
        }
    }
    size_t o = ((size_t)chunk * DIc + c) * DSc;
#pragma unroll
    for (int s = 0; s < DSc; s++) {
        g_He[o + s] = h[s];
        g_P[o + s] = ex2(sdt * A2[s]);
    }
}

// ---------------- kernel 8: cross-chunk combine -------------------------------
__global__ void k_combine() {
    int idx = blockIdx.x * blockDim.x + threadIdx.x;
    float h = 0.0f;
    for (int k = 0; k < NCH; k++) {
        size_t o = (size_t)k * DIc * DSc + idx;
        g_Hin[o] = h;
        h = fmaf(g_P[o], h, g_He[o]);
    }
}

// ---------------- kernel 9: scan pass 2 (inline dt; scalar; LC=128) -----------
__global__ void k_scan2(const float* __restrict__ A_log, const float* __restrict__ dtw,
                        const float* __restrict__ dtb, const float* __restrict__ Dskip) {
    int chunk = blockIdx.x;
    int c = threadIdx.x;
    __shared__ float U[LC][8];
    __shared__ float Bsh[LC][16];
    __shared__ float Csh[LC][16];
    int t0 = chunk * LC;
    {
        int row = threadIdx.x >> 1, q = threadIdx.x & 1;
        *(float4*)&U[row][q * 4] = *(const float4*)(g_dbc + (size_t)(t0 + row) * 64 + q * 4);
#pragma unroll
        for (int it = 0; it < 2; it++) {
            int v = threadIdx.x + it * 256;
            int r2 = v >> 2, q2 = v & 3;
            *(float4*)&Bsh[r2][q2 * 4] =
                *(const float4*)(g_dbc + (size_t)(t0 + r2) * 64 + 8 + q2 * 4);
            *(float4*)&Csh[r2][q2 * 4] =
                *(const float4*)(g_dbc + (size_t)(t0 + r2) * 64 + 24 + q2 * 4);
        }
    }
    __syncthreads();
    float w8[8];
#pragma unroll
    for (int k = 0; k < 8; k++) w8[k] = dtw[k * DIc + c];
    float b0 = dtb[c];
    float A2[DSc];
#pragma unroll
    for (int s = 0; s < DSc; s++) A2[s] = -__expf(A_log[c * DSc + s]) * LOG2E;
    float base = A2[0];
    bool structured = true;
#pragma unroll
    for (int s = 0; s < DSc; s++) {
        float e = base * (float)(s + 1);
        structured = structured && (fabsf(A2[s] - e) <= 1e-5f * fabsf(e) + 1e-30f);
    }
    float h[DSc];
    size_t oh = ((size_t)chunk * DIc + c) * DSc;
#pragma unroll
    for (int s = 0; s < DSc; s++) h[s] = g_Hin[oh + s];
    float dsk = Dskip[c];
    if (structured) {
#pragma unroll 2
        for (int t = 0; t < LC; t++) {
            float dot = b0;
#pragma unroll
            for (int k = 0; k < 8; k++) dot = fmaf(w8[k], U[t][k], dot);
            float d = softplus_fast(dot);
            float x = __bfloat162float(g_xcb[(size_t)(t0 + t) * DIc + c]);
            float z = __bfloat162float(g_xzb[(size_t)(t0 + t) * 512 + DIc + c]);
            float dx = d * x;
            float a[DSc];
            pow_chain(ex2(d * base), a);
            float acc = 0.0f;
#pragma unroll
            for (int s = 0; s < DSc; s++) {
                h[s] = fmaf(a[s], h[s], dx * Bsh[t][s]);
                acc = fmaf(h[s], Csh[t][s], acc);
            }
            acc = fmaf(dsk, x, acc);
            g_yb[(size_t)(t0 + t) * DIc + c] = __float2bfloat16(acc * silu_f(z));
        }
    } else {
#pragma unroll 2
        for (int t = 0; t < LC; t++) {
            float dot = b0;
#pragma unroll
            for (int k = 0; k < 8; k++) dot = fmaf(w8[k], U[t][k], dot);
            float d = softplus_fast(dot);
            float x = __bfloat162float(g_xcb[(size_t)(t0 + t) * DIc + c]);
            float z = __bfloat162float(g_xzb[(size_t)(t0 + t) * 512 + DIc + c]);
            float dx = d * x;
            float acc = 0.0f;
#pragma unroll
            for (int s = 0; s < DSc; s++) {
                float a = ex2(d * A2[s]);
                h[s] = fmaf(a, h[s], dx * Bsh[t][s]);
                acc = fmaf(h[s], Csh[t][s], acc);
            }
            acc = fmaf(dsk, x, acc);
            g_yb[(size_t)(t0 + t) * DIc + c] = __float2bfloat16(acc * silu_f(z));
        }
    }
}

// ---------------- kernel 10: fused out_proj + residual + LN + scatter ---------
__global__ void k_outln(const __nv_bfloat16* __restrict__ A, const __nv_bfloat16* __restrict__ B,
                        const float* __restrict__ resid, const int* __restrict__ perm,
                        const float* __restrict__ ln_w, const float* __restrict__ ln_b,
                        float* __restrict__ out) {
    constexpr int BK = 32, Kd = 256, Nc = 128;
    constexpr int LDA = 112;
    constexpr int LDB = 272;
    __shared__ __align__(16) unsigned char As[2][64 * LDA];
    __shared__ __align__(16) unsigned char Bs[2][BK * LDB];
    __shared__ float redA[64][2], redB[64][2];
    int tid = threadIdx.x;
    int lane = tid & 31;
    int warp = tid >> 5;
    int wr = warp & 3;
    int wc = warp >> 2;
    long row0 = (long)blockIdx.x * 64;

    float acc[8][4];
#pragma unroll
    for (int n = 0; n < 8; n++)
#pragma unroll
        for (int r = 0; r < 4; r++) acc[n][r] = 0.0f;

    uint32_t asb[2], bsb[2];
    asb[0] = (uint32_t)__cvta_generic_to_shared(&As[0][0]);
    asb[1] = (uint32_t)__cvta_generic_to_shared(&As[1][0]);
    bsb[0] = (uint32_t)__cvta_generic_to_shared(&Bs[0][0]);
    bsb[1] = (uint32_t)__cvta_generic_to_shared(&Bs[1][0]);

    int ar = tid >> 2, ac = tid & 3;
    int br = tid >> 3, bc = tid & 7;

    auto issue = [&](int buf, int k0) {
        cpa16(asb[buf] + ar * LDA + ac * 16, A + (row0 + ar) * Kd + k0 + ac * 8);
        cpa16(bsb[buf] + br * LDB + bc * 16, B + (long)(k0 + br) * Nc + bc * 8);
        cpa16(bsb[buf] + br * LDB + 128 + bc * 16, B + (long)(k0 + br) * Nc + 64 + bc * 8);
        cp_commit();
    };

    issue(0, 0);
    int buf = 0;
    int a_row_in_tile = lane & 15;
    int a_colh = (lane >> 4) << 3;
    int b_krow = (lane & 7) + (((lane >> 3) & 1) << 3);
    int b_ncol = (lane >> 4) << 3;

    constexpr int KT = Kd / BK;
    for (int kt = 0; kt < KT; kt++) {
        if (kt + 1 < KT) {
            issue(buf ^ 1, (kt + 1) * BK);
            cp_wait<1>();
        } else {
            cp_wait<0>();
        }
        __syncthreads();
#pragma unroll
        for (int ks = 0; ks < 2; ks++) {
            int kh = ks * 16;
            uint32_t a[4];
            {
                int row = wr * 16 + a_row_in_tile;
                ldsm4(a[0], a[1], a[2], a[3], asb[buf] + row * LDA + (kh + a_colh) * 2);
            }
            uint32_t b[8][2];
#pragma unroll
            for (int np = 0; np < 4; np++) {
                int krow = kh + b_krow;
                int ncol = wc * 64 + np * 16 + b_ncol;
                uint32_t r0, r1, r2, r3;
                ldsm4t(r0, r1, r2, r3, bsb[buf] + krow * LDB + ncol * 2);
                b[np * 2][0] = r0;
                b[np * 2][1] = r1;
                b[np * 2 + 1][0] = r2;
                b[np * 2 + 1][1] = r3;
            }
#pragma unroll
            for (int nt = 0; nt < 8; nt++) mma_bf16(acc[nt], a, b[nt]);
        }
        __syncthreads();
        buf ^= 1;
    }

    int g = lane >> 2;
    int tg = lane & 3;
    int rA = wr * 16 + g;
    int rB = rA + 8;
    float va[16], vb[16];
    float s1a = 0.f, s2a = 0.f, s1b = 0.f, s2b = 0.f;
#pragma unroll
    for (int nt = 0; nt < 8; nt++) {
        int cc = wc * 64 + nt * 8 + tg * 2;
        float2 sa = *(const float2*)(resid + (row0 + rA) * Nc + cc);
        float2 sb = *(const float2*)(resid + (row0 + rB) * Nc + cc);
        float x0 = acc[nt][0] + sa.x, x1 = acc[nt][1] + sa.y;
        float x2 = acc[nt][2] + sb.x, x3 = acc[nt][3] + sb.y;
        va[nt * 2] = x0; va[nt * 2 + 1] = x1;
        vb[nt * 2] = x2; vb[nt * 2 + 1] = x3;
        s1a += x0 + x1; s2a += x0 * x0 + x1 * x1;
        s1b += x2 + x3; s2b += x2 * x2 + x3 * x3;
    }
#pragma unroll
    for (int o = 1; o <= 2; o <<= 1) {
        s1a += __shfl_xor_sync(0xffffffffu, s1a, o);
        s2a += __shfl_xor_sync(0xffffffffu, s2a, o);
        s1b += __shfl_xor_sync(0xffffffffu, s1b, o);
        s2b += __shfl_xor_sync(0xffffffffu, s2b, o);
    }
    if (tg == 0) {
        redA[rA][wc] = s1a; redB[rA][wc] = s2a;
        redA[rB][wc] = s1b; redB[rB][wc] = s2b;
    }
    __syncthreads();
    float muA = (redA[rA][0] + redA[rA][1]) * (1.0f / 128.0f);
    float e2A = (redB[rA][0] + redB[rA][1]) * (1.0f / 128.0f);
    float muB = (redA[rB][0] + redA[rB][1]) * (1.0f / 128.0f);
    float e2B = (redB[rB][0] + redB[rB][1]) * (1.0f / 128.0f);
    float rsA = rsqrtf(e2A - muA * muA + EPSF);
    float rsB = rsqrtf(e2B - muB * muB + EPSF);
    int prA = perm[row0 + rA];
    int prB = perm[row0 + rB];
#pragma unroll
    for (int nt = 0; nt < 8; nt++) {
        int cc = wc * 64 + nt * 8 + tg * 2;
        float2 w = *(const float2*)(ln_w + cc);
        float2 bb = *(const float2*)(ln_b + cc);
        float2 oa, ob;
        oa.x = (va[nt * 2] - muA) * rsA * w.x + bb.x;
        oa.y = (va[nt * 2 + 1] - muA) * rsA * w.y + bb.y;
        ob.x = (vb[nt * 2] - muB) * rsB * w.x + bb.x;
        ob.y = (vb[nt * 2 + 1] - muB) * rsB * w.y + bb.y;
        *(float2*)(out + (size_t)prA * Nc + cc) = oa;
        *(float2*)(out + (size_t)prB * Nc + cc) = ob;
    }
}

// ---------------- host ---------------------------------------------------------
extern "C" void kernel_launch(void* const* d_in, const int* in_sizes, int n_in,
                              void* d_out, int out_size) {
    const float *vf, *pos_w, *pos_b, *rms_w, *in_proj_w, *conv_w, *conv_b, *x_proj_w;
    const float *dt_w, *dt_b, *A_log, *Dskip, *out_proj_w, *ln_w, *ln_b;
    const int *coords, *perm, *inv_perm;

    if (in_sizes[1] == NN * 4) {
        vf = (const float*)d_in[0];
        coords = (const int*)d_in[1];
        perm = (const int*)d_in[2];
        inv_perm = (const int*)d_in[3];
        pos_w = (const float*)d_in[4];
        pos_b = (const float*)d_in[5];
        rms_w = (const float*)d_in[6];
        in_proj_w = (const float*)d_in[7];
        conv_w = (const float*)d_in[8];
        conv_b = (const float*)d_in[9];
        x_proj_w = (const float*)d_in[10];
        dt_w = (const float*)d_in[11];
        dt_b = (const float*)d_in[12];
        A_log = (const float*)d_in[13];
        Dskip = (const float*)d_in[14];
        out_proj_w = (const float*)d_in[15];
        ln_w = (const float*)d_in[16];
        ln_b = (const float*)d_in[17];
    } else {
        vf = (const float*)d_in[0];
        pos_w = (const float*)d_in[1];
        pos_b = (const float*)d_in[2];
        rms_w = (const float*)d_in[3];
        in_proj_w = (const float*)d_in[4];
        conv_w = (const float*)d_in[5];
        conv_b = (const float*)d_in[6];
        x_proj_w = (const float*)d_in[7];
        dt_w = (const float*)d_in[8];
        dt_b = (const float*)d_in[9];
        A_log = (const float*)d_in[10];
        Dskip = (const float*)d_in[11];
        out_proj_w = (const float*)d_in[12];
        ln_w = (const float*)d_in[13];
        ln_b = (const float*)d_in[14];
        coords = (const int*)d_in[15];
        perm = (const int*)d_in[16];
        inv_perm = (const int*)d_in[17];
    }
    (void)inv_perm;

    void *p_rmsb, *p_xzb, *p_xcb, *p_dbc, *p_yb, *p_resid, *p_w1b, *p_w2b, *p_w3b;
    cudaGetSymbolAddress(&p_rmsb, g_rmsb);
    cudaGetSymbolAddress(&p_xzb, g_xzb);
    cudaGetSymbolAddress(&p_xcb, g_xcb);
    cudaGetSymbolAddress(&p_dbc, g_dbc);
    cudaGetSymbolAddress(&p_yb, g_yb);
    cudaGetSymbolAddress(&p_resid, g_resid);
    cudaGetSymbolAddress(&p_w1b, g_w1b);
    cudaGetSymbolAddress(&p_w2b, g_w2b);
    cudaGetSymbolAddress(&p_w3b, g_w3b);

    k_wcvt<<<448, 256>>>(in_proj_w, x_proj_w, out_proj_w);
    k_pre<<<NN, 128>>>(vf, coords, perm, pos_w, pos_b, rms_w);
    bgemm<2, true, 512, 128><<<dim3(NN / 128, 512 / 64), 256>>>(
        (const __nv_bfloat16*)p_rmsb, (const __nv_bfloat16*)p_w1b, p_xzb);
    k_conv<<<(NN / 16), 256>>>(conv_w, conv_b);
    bgemm<1, false, 64, 256><<<dim3(NN / 64, 1), 256>>>(
        (const __nv_bfloat16*)p_xcb, (const __nv_bfloat16*)p_w2b, p_dbc);
    k_scan1<<<NCH, DIc>>>(A_log, dt_w, dt_b);
    k_combine<<<DIc * DSc / 256, 256>>>();
    k_scan2<<<NCH, DIc>>>(A_log, dt_w, dt_b, Dskip);
    k_outln<<<NN / 64, 256>>>((const __nv_bfloat16*)p_yb, (const __nv_bfloat16*)p_w3b,
                              (const float*)p_resid, perm, ln_w, ln_b, (float*)d_out);
    (void)n_in;
    (void)out_size;
    (void)in_sizes;
}

// round 15
// speedup vs baseline: 1.4597x; 1.0321x over previous
#include <cuda_runtime.h>
#include <cuda_bf16.h>
#include <cstdint>

#define NN 32768
#define DD 128
#define DIc 256
#define DSc 16
#define LC 128
#define NCH (NN / LC)
#define EPSF 1e-5f
#define LOG2E 1.4426950408889634f
#define LN2F 0.6931471805599453f

// ---------------- scratch (device globals; no allocation allowed) -------------
__device__ float g_resid[NN * DD];
__device__ __nv_bfloat16 g_rmsb[NN * DD];
__device__ __nv_bfloat16 g_xzb[NN * 2 * DIc];
__device__ __nv_bfloat16 g_xcb[NN * DIc];
__device__ float g_dbc[NN * 64];
__device__ float g_P[NCH * DIc * DSc];
__device__ float g_He[NCH * DIc * DSc];
__device__ float g_Hin[NCH * DIc * DSc];
__device__ __nv_bfloat16 g_yb[NN * DIc];
__device__ __nv_bfloat16 g_w1b[DD * 512];
__device__ __nv_bfloat16 g_w2b[DIc * 64];
__device__ __nv_bfloat16 g_w3b[DIc * DD];

// ---------------- helpers -----------------------------------------------------
__device__ __forceinline__ float ex2(float x) {
    float y;
    asm("ex2.approx.ftz.f32 %0, %1;" : "=f"(y) : "f"(x));
    return y;
}
__device__ __forceinline__ float lg2(float x) {
    float y;
    asm("lg2.approx.ftz.f32 %0, %1;" : "=f"(y) : "f"(x));
    return y;
}
__device__ __forceinline__ float fexp(float x) { return ex2(x * LOG2E); }
__device__ __forceinline__ float silu_f(float x) { return x / (1.0f + fexp(-x)); }
__device__ __forceinline__ float softplus_fast(float v) {
    float t = ex2(v * LOG2E);
    float r = LN2F * lg2(1.0f + t);
    return v > 20.0f ? v : r;
}
__device__ __forceinline__ void ldsm4(uint32_t& r0, uint32_t& r1, uint32_t& r2, uint32_t& r3,
                                      uint32_t a) {
    asm volatile("ldmatrix.sync.aligned.m8n8.x4.shared.b16 {%0,%1,%2,%3},[%4];"
                 : "=r"(r0), "=r"(r1), "=r"(r2), "=r"(r3)
                 : "r"(a));
}
__device__ __forceinline__ void ldsm4t(uint32_t& r0, uint32_t& r1, uint32_t& r2, uint32_t& r3,
                                       uint32_t a) {
    asm volatile("ldmatrix.sync.aligned.m8n8.x4.trans.shared.b16 {%0,%1,%2,%3},[%4];"
                 : "=r"(r0), "=r"(r1), "=r"(r2), "=r"(r3)
                 : "r"(a));
}
__device__ __forceinline__ void mma_bf16(float* c, const uint32_t* a, const uint32_t* b) {
    asm volatile(
        "mma.sync.aligned.m16n8k16.row.col.f32.bf16.bf16.f32 "
        "{%0,%1,%2,%3},{%4,%5,%6,%7},{%8,%9},{%0,%1,%2,%3};"
        : "+f"(c[0]), "+f"(c[1]), "+f"(c[2]), "+f"(c[3])
        : "r"(a[0]), "r"(a[1]), "r"(a[2]), "r"(a[3]), "r"(b[0]), "r"(b[1]));
}
__device__ __forceinline__ void cpa16(uint32_t s, const void* g) {
    asm volatile("cp.async.cg.shared.global [%0], [%1], 16;" ::"r"(s), "l"(g));
}
__device__ __forceinline__ void cp_commit() { asm volatile("cp.async.commit_group;"); }
template <int NG>
__device__ __forceinline__ void cp_wait() {
    asm volatile("cp.async.wait_group %0;" ::"n"(NG));
}
// r^(s+1) for s=0..15, log-depth (scalar — verified faster than f32x2 pairs on B300)
__device__ __forceinline__ void pow_chain(float r, float* a) {
    a[0] = r;
    a[1] = r * r;
    a[2] = a[1] * r;
    a[3] = a[1] * a[1];
    a[4] = a[3] * r;
    a[5] = a[2] * a[2];
    a[6] = a[5] * r;
    a[7] = a[3] * a[3];
    a[8] = a[7] * r;
    a[9] = a[4] * a[4];
    a[10] = a[9] * r;
    a[11] = a[5] * a[5];
    a[12] = a[11] * r;
    a[13] = a[6] * a[6];
    a[14] = a[13] * r;
    a[15] = a[7] * a[7];
}

// ---------------- kernel 0: convert weights to bf16 (+ pad x_proj) ------------
__global__ void k_wcvt(const float* __restrict__ w1, const float* __restrict__ xw,
                       const float* __restrict__ w3) {
    int idx = blockIdx.x * blockDim.x + threadIdx.x;
    if (idx < DD * 512) {
        g_w1b[idx] = __float2bfloat16(w1[idx]);
    } else if (idx < DD * 512 + DIc * 64) {
        int i = idx - DD * 512;
        int k = i >> 6, j = i & 63;
        g_w2b[i] = __float2bfloat16(j < 40 ? xw[k * 40 + j] : 0.0f);
    } else {
        int i = idx - DD * 512 - DIc * 64;
        g_w3b[i] = __float2bfloat16(w3[i]);
    }
}

// ---------------- kernel 1: pos-encode + gather(perm) + RMSNorm ---------------
__global__ void k_pre(const float* __restrict__ vf, const int* __restrict__ coords,
                      const int* __restrict__ perm, const float* __restrict__ pos_w,
                      const float* __restrict__ pos_b, const float* __restrict__ rms_w) {
    int i = blockIdx.x;
    int d = threadIdx.x;  // 128
    int j = perm[i];
    int cz = coords[j * 4 + 1];
    int cy = coords[j * 4 + 2];
    int cx = coords[j * 4 + 3];
    const float dnm = 1.0f / 43.0f;
    const float t12 = 1.0f / 12.0f;
    float pf[9];
    pf[0] = (float)cz * (1.0f / 16.0f);
    pf[1] = (float)(cy / 12) * dnm;
    pf[2] = (float)(cx / 12) * dnm;
    pf[3] = (float)(cy % 12) * t12;
    pf[4] = (float)(cx % 12) * t12;
    pf[5] = (float)((cy + 6) / 12) * dnm;
    pf[6] = (float)((cx + 6) / 12) * dnm;
    pf[7] = (float)((cy + 6) % 12) * t12;
    pf[8] = (float)((cx + 6) % 12) * t12;
    float pe = pos_b[d];
#pragma unroll
    for (int f = 0; f < 9; f++) pe = fmaf(pf[f], pos_w[f * DD + d], pe);
    float val = vf[(size_t)j * DD + d] + pe;
    g_resid[(size_t)i * DD + d] = val;

    float v2 = val * val;
#pragma unroll
    for (int o = 16; o > 0; o >>= 1) v2 += __shfl_xor_sync(0xffffffffu, v2, o);
    __shared__ float red[4];
    if ((d & 31) == 0) red[d >> 5] = v2;
    __syncthreads();
    float ms = (red[0] + red[1] + red[2] + red[3]) * (1.0f / 128.0f);
    g_rmsb[(size_t)i * DD + d] = __float2bfloat16(val * rsqrtf(ms + EPSF) * rms_w[d]);
}

// ---------------- bf16 TC GEMM, cp.async double-buffered (runtime Nc/Kd) ------
template <int MT, bool OUTB>
__global__ void bgemm(const __nv_bfloat16* __restrict__ A, const __nv_bfloat16* __restrict__ B,
                      void* __restrict__ Cout, int Nc, int Kd) {
    constexpr int BM = MT * 64;
    constexpr int BK = 32;
    constexpr int LDA = 112;
    constexpr int LDB = 144;
    __shared__ __align__(16) unsigned char As[2][BM * LDA];
    __shared__ __align__(16) unsigned char Bs[2][BK * LDB];
    int tid = threadIdx.x;
    int lane = tid & 31;
    int warp = tid >> 5;
    int wr = warp & 3;
    int wc = warp >> 2;
    long row0 = (long)blockIdx.x * BM;
    int col0 = blockIdx.y * 64;

    float acc[MT][4][4];
#pragma unroll
    for (int m = 0; m < MT; m++)
#pragma unroll
        for (int n = 0; n < 4; n++)
#pragma unroll
            for (int r = 0; r < 4; r++) acc[m][n][r] = 0.0f;

    uint32_t asb[2], bsb[2];
    asb[0] = (uint32_t)__cvta_generic_to_shared(&As[0][0]);
    asb[1] = (uint32_t)__cvta_generic_to_shared(&As[1][0]);
    bsb[0] = (uint32_t)__cvta_generic_to_shared(&Bs[0][0]);
    bsb[1] = (uint32_t)__cvta_generic_to_shared(&Bs[1][0]);

    int ar = tid >> 2, ac = tid & 3;
    int br = tid >> 3, bc = tid & 7;

    auto issue = [&](int buf, int k0) {
#pragma unroll
        for (int it = 0; it < MT; it++) {
            int r = ar + it * 64;
            cpa16(asb[buf] + r * LDA + ac * 16, A + (row0 + r) * Kd + k0 + ac * 8);
        }
        cpa16(bsb[buf] + br * LDB + bc * 16, B + (long)(k0 + br) * Nc + col0 + bc * 8);
        cp_commit();
    };

    int KT = Kd / BK;
    issue(0, 0);
    int buf = 0;

    int a_row_in_tile = lane & 15;
    int a_colh = (lane >> 4) << 3;
    int b_krow = (lane & 7) + (((lane >> 3) & 1) << 3);
    int b_ncol = (lane >> 4) << 3;

    for (int kt = 0; kt < KT; kt++) {
        if (kt + 1 < KT) {
            issue(buf ^ 1, (kt + 1) * BK);
            cp_wait<1>();
        } else {
            cp_wait<0>();
        }
        __syncthreads();
#pragma unroll
        for (int ks = 0; ks < 2; ks++) {
            int kh = ks * 16;
            uint32_t a[MT][4];
#pragma unroll
            for (int mt = 0; mt < MT; mt++) {
                int row = wr * (MT * 16) + mt * 16 + a_row_in_tile;
                ldsm4(a[mt][0], a[mt][1], a[mt][2], a[mt][3],
                      asb[buf] + row * LDA + (kh + a_colh) * 2);
            }
            uint32_t b[4][2];
#pragma unroll
            for (int np = 0; np < 2; np++) {
                int krow = kh + b_krow;
                int ncol = wc * 32 + np * 16 + b_ncol;
                uint32_t r0, r1, r2, r3;
                ldsm4t(r0, r1, r2, r3, bsb[buf] + krow * LDB + ncol * 2);
                b[np * 2][0] = r0;
                b[np * 2][1] = r1;
                b[np * 2 + 1][0] = r2;
                b[np * 2 + 1][1] = r3;
            }
#pragma unroll
            for (int mt = 0; mt < MT; mt++)
#pragma unroll
                for (int nt = 0; nt < 4; nt++) mma_bf16(acc[mt][nt], a[mt], b[nt]);
        }
        __syncthreads();
        buf ^= 1;
    }

    int g = lane >> 2;
    int tg = lane & 3;
#pragma unroll
    for (int mt = 0; mt < MT; mt++) {
#pragma unroll
        for (int nt = 0; nt < 4; nt++) {
            long r0 = row0 + wr * (MT * 16) + mt * 16 + g;
            int c = col0 + wc * 32 + nt * 8 + tg * 2;
            if (OUTB) {
                __nv_bfloat16* C = (__nv_bfloat16*)Cout;
                *(__nv_bfloat162*)(C + r0 * Nc + c) =
                    __float22bfloat162_rn(make_float2(acc[mt][nt][0], acc[mt][nt][1]));
                *(__nv_bfloat162*)(C + (r0 + 8) * Nc + c) =
                    __float22bfloat162_rn(make_float2(acc[mt][nt][2], acc[mt][nt][3]));
            } else {
                float* C = (float*)Cout;
                *(float2*)(C + r0 * Nc + c) = make_float2(acc[mt][nt][0], acc[mt][nt][1]);
                *(float2*)(C + (r0 + 8) * Nc + c) = make_float2(acc[mt][nt][2], acc[mt][nt][3]);
            }
        }
    }
}

// ---------------- kernel 3: causal conv — 2 channels/thread, bf16x2 I/O -------
__global__ void k_conv(const float* __restrict__ conv_w, const float* __restrict__ conv_b) {
    int idx = blockIdx.x * blockDim.x + threadIdx.x;  // (NN/8)*128
    int tb = idx >> 7;
    int cp = idx & 127;
    int c = cp * 2;
    int t0 = tb * 8;
    float4 wA = *(const float4*)(conv_w + c * 4);
    float4 wB = *(const float4*)(conv_w + c * 4 + 4);
    float2 bias = *(const float2*)(conv_b + c);
    float2 v[11];
#pragma unroll
    for (int i = 0; i < 11; i++) {
        int t = t0 - 3 + i;
        if (t >= 0) {
            __nv_bfloat162 h = *(const __nv_bfloat162*)(g_xzb + (size_t)t * 512 + c);
            v[i] = __bfloat1622float2(h);
        } else {
            v[i] = make_float2(0.0f, 0.0f);
        }
    }
#pragma unroll
    for (int j = 0; j < 8; j++) {
        float sa = bias.x, sb = bias.y;
        sa = fmaf(wA.x, v[j].x, sa);
        sb = fmaf(wB.x, v[j].y, sb);
        sa = fmaf(wA.y, v[j + 1].x, sa);
        sb = fmaf(wB.y, v[j + 1].y, sb);
        sa = fmaf(wA.z, v[j + 2].x, sa);
        sb = fmaf(wB.z, v[j + 2].y, sb);
        sa = fmaf(wA.w, v[j + 3].x, sa);
        sb = fmaf(wB.w, v[j + 3].y, sb);
        *(__nv_bfloat162*)(g_xcb + (size_t)(t0 + j) * DIc + c) =
            __float22bfloat162_rn(make_float2(silu_f(sa), silu_f(sb)));
    }
}

// ---------------- kernel 7: scan pass 1 (inline dt; scalar; LC=128) -----------
__global__ void k_scan1(const float* __restrict__ A_log, const float* __restrict__ dtw,
                        const float* __restrict__ dtb) {
    int chunk = blockIdx.x;
    int c = threadIdx.x;
    __shared__ float U[LC][8];
    __shared__ float Bsh[LC][16];
    int t0 = chunk * LC;
    {
        int row = threadIdx.x >> 1, q = threadIdx.x & 1;
        *(float4*)&U[row][q * 4] = *(const float4*)(g_dbc + (size_t)(t0 + row) * 64 + q * 4);
#pragma unroll
        for (int it = 0; it < 2; it++) {
            int v = threadIdx.x + it * 256;
            int r2 = v >> 2, q2 = v & 3;
            *(float4*)&Bsh[r2][q2 * 4] =
                *(const float4*)(g_dbc + (size_t)(t0 + r2) * 64 + 8 + q2 * 4);
        }
    }
    __syncthreads();
    float w8[8];
#pragma unroll
    for (int k = 0; k < 8; k++) w8[k] = dtw[k * DIc + c];
    float b0 = dtb[c];
    float A2[DSc];
#pragma unroll
    for (int s = 0; s < DSc; s++) A2[s] = -__expf(A_log[c * DSc + s]) * LOG2E;
    float base = A2[0];
    bool structured = true;
#pragma unroll
    for (int s = 0; s < DSc; s++) {
        float e = base * (float)(s + 1);
        structured = structured && (fabsf(A2[s] - e) <= 1e-5f * fabsf(e) + 1e-30f);
    }
    float h[DSc];
#pragma unroll
    for (int s = 0; s < DSc; s++) h[s] = 0.0f;
    float sdt = 0.0f;
    if (structured) {
#pragma unroll 2
        for (int t = 0; t < LC; t++) {
            float dot = b0;
#pragma unroll
            for (int k = 0; k < 8; k++) dot = fmaf(w8[k], U[t][k], dot);
            float d = softplus_fast(dot);
            float x = __bfloat162float(g_xcb[(size_t)(t0 + t) * DIc + c]);
            float dx = d * x;
            sdt += d;
            float a[DSc];
            pow_chain(ex2(d * base), a);
#pragma unroll
            for (int s = 0; s < DSc; s++) h[s] = fmaf(a[s], h[s], dx * Bsh[t][s]);
        }
    } else {
#pragma unroll 2
        for (int t = 0; t < LC; t++) {
            float dot = b0;
#pragma unroll
            for (int k = 0; k < 8; k++) dot = fmaf(w8[k], U[t][k], dot);
            float d = softplus_fast(dot);
            float x = __bfloat162float(g_xcb[(size_t)(t0 + t) * DIc + c]);
            float dx = d * x;
            sdt += d;
#pragma unroll
            for (int s = 0; s < DSc; s++) {
                float a = ex2(d * A2[s]);
                h[s] = fmaf(a, h[s], dx * Bsh[t][s]);
            }
        }
    }
    size_t o = ((size_t)chunk * DIc + c) * DSc;
#pragma unroll
    for (int s = 0; s < DSc; s++) {
        g_He[o + s] = h[s];
        g_P[o + s] = ex2(sdt * A2[s]);
    }
}

// ---------------- kernel 8: cross-chunk combine -------------------------------
__global__ void k_combine() {
    int idx = blockIdx.x * blockDim.x + threadIdx.x;
    float h = 0.0f;
    for (int k = 0; k < NCH; k++) {
        size_t o = (size_t)k * DIc * DSc + idx;
        g_Hin[o] = h;
        h = fmaf(g_P[o], h, g_He[o]);
    }
}

// ---------------- kernel 9: scan pass 2 (inline dt; scalar; LC=128) -----------
__global__ void k_scan2(const float* __restrict__ A_log, const float* __restrict__ dtw,
                        const float* __restrict__ dtb, const float* __restrict__ Dskip) {
    int chunk = blockIdx.x;
    int c = threadIdx.x;
    __shared__ float U[LC][8];
    __shared__ float Bsh[LC][16];
    __shared__ float Csh[LC][16];
    int t0 = chunk * LC;
    {
        int row = threadIdx.x >> 1, q = threadIdx.x & 1;
        *(float4*)&U[row][q * 4] = *(const float4*)(g_dbc + (size_t)(t0 + row) * 64 + q * 4);
#pragma unroll
        for (int it = 0; it < 2; it++) {
            int v = threadIdx.x + it * 256;
            int r2 = v >> 2, q2 = v & 3;
            *(float4*)&Bsh[r2][q2 * 4] =
                *(const float4*)(g_dbc + (size_t)(t0 + r2) * 64 + 8 + q2 * 4);
            *(float4*)&Csh[r2][q2 * 4] =
                *(const float4*)(g_dbc + (size_t)(t0 + r2) * 64 + 24 + q2 * 4);
        }
    }
    __syncthreads();
    float w8[8];
#pragma unroll
    for (int k = 0; k < 8; k++) w8[k] = dtw[k * DIc + c];
    float b0 = dtb[c];
    float A2[DSc];
#pragma unroll
    for (int s = 0; s < DSc; s++) A2[s] = -__expf(A_log[c * DSc + s]) * LOG2E;
    float base = A2[0];
    bool structured = true;
#pragma unroll
    for (int s = 0; s < DSc; s++) {
        float e = base * (float)(s + 1);
        structured = structured && (fabsf(A2[s] - e) <= 1e-5f * fabsf(e) + 1e-30f);
    }
    float h[DSc];
    size_t oh = ((size_t)chunk * DIc + c) * DSc;
#pragma unroll
    for (int s = 0; s < DSc; s++) h[s] = g_Hin[oh + s];
    float dsk = Dskip[c];
    if (structured) {
#pragma unroll 2
        for (int t = 0; t < LC; t++) {
            float dot = b0;
#pragma unroll
            for (int k = 0; k < 8; k++) dot = fmaf(w8[k], U[t][k], dot);
            float d = softplus_fast(dot);
            float x = __bfloat162float(g_xcb[(size_t)(t0 + t) * DIc + c]);
            float z = __bfloat162float(g_xzb[(size_t)(t0 + t) * 512 + DIc + c]);
            float dx = d * x;
            float a[DSc];
            pow_chain(ex2(d * base), a);
            float acc = 0.0f;
#pragma unroll
            for (int s = 0; s < DSc; s++) {
                h[s] = fmaf(a[s], h[s], dx * Bsh[t][s]);
                acc = fmaf(h[s], Csh[t][s], acc);
            }
            acc = fmaf(dsk, x, acc);
            g_yb[(size_t)(t0 + t) * DIc + c] = __float2bfloat16(acc * silu_f(z));
        }
    } else {
#pragma unroll 2
        for (int t = 0; t < LC; t++) {
            float dot = b0;
#pragma unroll
            for (int k = 0; k < 8; k++) dot = fmaf(w8[k], U[t][k], dot);
            float d = softplus_fast(dot);
            float x = __bfloat162float(g_xcb[(size_t)(t0 + t) * DIc + c]);
            float z = __bfloat162float(g_xzb[(size_t)(t0 + t) * 512 + DIc + c]);
            float dx = d * x;
            float acc = 0.0f;
#pragma unroll
            for (int s = 0; s < DSc; s++) {
                float a = ex2(d * A2[s]);
                h[s] = fmaf(a, h[s], dx * Bsh[t][s]);
                acc = fmaf(h[s], Csh[t][s], acc);
            }
            acc = fmaf(dsk, x, acc);
            g_yb[(size_t)(t0 + t) * DIc + c] = __float2bfloat16(acc * silu_f(z));
        }
    }
}

// ---------------- kernel 10: fused out_proj + residual + LN + scatter ---------
__global__ void k_outln(const __nv_bfloat16* __restrict__ A, const __nv_bfloat16* __restrict__ B,
                        const float* __restrict__ resid, const int* __restrict__ perm,
                        const float* __restrict__ ln_w, const float* __restrict__ ln_b,
                        float* __restrict__ out) {
    constexpr int BK = 32, Kd = 256, Nc = 128;
    constexpr int LDA = 112;
    constexpr int LDB = 272;
    __shared__ __align__(16) unsigned char As[2][64 * LDA];
    __shared__ __align__(16) unsigned char Bs[2][BK * LDB];
    __shared__ float redA[64][2], redB[64][2];
    int tid = threadIdx.x;
    int lane = tid & 31;
    int warp = tid >> 5;
    int wr = warp & 3;
    int wc = warp >> 2;
    long row0 = (long)blockIdx.x * 64;

    float acc[8][4];
#pragma unroll
    for (int n = 0; n < 8; n++)
#pragma unroll
        for (int r = 0; r < 4; r++) acc[n][r] = 0.0f;

    uint32_t asb[2], bsb[2];
    asb[0] = (uint32_t)__cvta_generic_to_shared(&As[0][0]);
    asb[1] = (uint32_t)__cvta_generic_to_shared(&As[1][0]);
    bsb[0] = (uint32_t)__cvta_generic_to_shared(&Bs[0][0]);
    bsb[1] = (uint32_t)__cvta_generic_to_shared(&Bs[1][0]);

    int ar = tid >> 2, ac = tid & 3;
    int br = tid >> 3, bc = tid & 7;

    auto issue = [&](int buf, int k0) {
        cpa16(asb[buf] + ar * LDA + ac * 16, A + (row0 + ar) * Kd + k0 + ac * 8);
        cpa16(bsb[buf] + br * LDB + bc * 16, B + (long)(k0 + br) * Nc + bc * 8);
        cpa16(bsb[buf] + br * LDB + 128 + bc * 16, B + (long)(k0 + br) * Nc + 64 + bc * 8);
        cp_commit();
    };

    issue(0, 0);
    int buf = 0;
    int a_row_in_tile = lane & 15;
    int a_colh = (lane >> 4) << 3;
    int b_krow = (lane & 7) + (((lane >> 3) & 1) << 3);
    int b_ncol = (lane >> 4) << 3;

    constexpr int KT = Kd / BK;
    for (int kt = 0; kt < KT; kt++) {
        if (kt + 1 < KT) {
            issue(buf ^ 1, (kt + 1) * BK);
            cp_wait<1>();
        } else {
            cp_wait<0>();
        }
        __syncthreads();
#pragma unroll
        for (int ks = 0; ks < 2; ks++) {
            int kh = ks * 16;
            uint32_t a[4];
            {
                int row = wr * 16 + a_row_in_tile;
                ldsm4(a[0], a[1], a[2], a[3], asb[buf] + row * LDA + (kh + a_colh) * 2);
            }
            uint32_t b[8][2];
#pragma unroll
            for (int np = 0; np < 4; np++) {
                int krow = kh + b_krow;
                int ncol = wc * 64 + np * 16 + b_ncol;
                uint32_t r0, r1, r2, r3;
                ldsm4t(r0, r1, r2, r3, bsb[buf] + krow * LDB + ncol * 2);
                b[np * 2][0] = r0;
                b[np * 2][1] = r1;
                b[np * 2 + 1][0] = r2;
                b[np * 2 + 1][1] = r3;
            }
#pragma unroll
            for (int nt = 0; nt < 8; nt++) mma_bf16(acc[nt], a, b[nt]);
        }
        __syncthreads();
        buf ^= 1;
    }

    int g = lane >> 2;
    int tg = lane & 3;
    int rA = wr * 16 + g;
    int rB = rA + 8;
    float va[16], vb[16];
    float s1a = 0.f, s2a = 0.f, s1b = 0.f, s2b = 0.f;
#pragma unroll
    for (int nt = 0; nt < 8; nt++) {
        int cc = wc * 64 + nt * 8 + tg * 2;
        float2 sa = *(const float2*)(resid + (row0 + rA) * Nc + cc);
        float2 sb = *(const float2*)(resid + (row0 + rB) * Nc + cc);
        float x0 = acc[nt][0] + sa.x, x1 = acc[nt][1] + sa.y;
        float x2 = acc[nt][2] + sb.x, x3 = acc[nt][3] + sb.y;
        va[nt * 2] = x0; va[nt * 2 + 1] = x1;
        vb[nt * 2] = x2; vb[nt * 2 + 1] = x3;
        s1a += x0 + x1; s2a += x0 * x0 + x1 * x1;
        s1b += x2 + x3; s2b += x2 * x2 + x3 * x3;
    }
#pragma unroll
    for (int o = 1; o <= 2; o <<= 1) {
        s1a += __shfl_xor_sync(0xffffffffu, s1a, o);
        s2a += __shfl_xor_sync(0xffffffffu, s2a, o);
        s1b += __shfl_xor_sync(0xffffffffu, s1b, o);
        s2b += __shfl_xor_sync(0xffffffffu, s2b, o);
    }
    if (tg == 0) {
        redA[rA][wc] = s1a; redB[rA][wc] = s2a;
        redA[rB][wc] = s1b; redB[rB][wc] = s2b;
    }
    __syncthreads();
    float muA = (redA[rA][0] + redA[rA][1]) * (1.0f / 128.0f);
    float e2A = (redB[rA][0] + redB[rA][1]) * (1.0f / 128.0f);
    float muB = (redA[rB][0] + redA[rB][1]) * (1.0f / 128.0f);
    float e2B = (redB[rB][0] + redB[rB][1]) * (1.0f / 128.0f);
    float rsA = rsqrtf(e2A - muA * muA + EPSF);
    float rsB = rsqrtf(e2B - muB * muB + EPSF);
    int prA = perm[row0 + rA];
    int prB = perm[row0 + rB];
#pragma unroll
    for (int nt = 0; nt < 8; nt++) {
        int cc = wc * 64 + nt * 8 + tg * 2;
        float2 w = *(const float2*)(ln_w + cc);
        float2 bb = *(const float2*)(ln_b + cc);
        float2 oa, ob;
        oa.x = (va[nt * 2] - muA) * rsA * w.x + bb.x;
        oa.y = (va[nt * 2 + 1] - muA) * rsA * w.y + bb.y;
        ob.x = (vb[nt * 2] - muB) * rsB * w.x + bb.x;
        ob.y = (vb[nt * 2 + 1] - muB) * rsB * w.y + bb.y;
        *(float2*)(out + (size_t)prA * Nc + cc) = oa;
        *(float2*)(out + (size_t)prB * Nc + cc) = ob;
    }
}

// ---------------- host ---------------------------------------------------------
extern "C" void kernel_launch(void* const* d_in, const int* in_sizes, int n_in,
                              void* d_out, int out_size) {
    const float *vf, *pos_w, *pos_b, *rms_w, *in_proj_w, *conv_w, *conv_b, *x_proj_w;
    const float *dt_w, *dt_b, *A_log, *Dskip, *out_proj_w, *ln_w, *ln_b;
    const int *coords, *perm, *inv_perm;

    if (in_sizes[1] == NN * 4) {
        vf = (const float*)d_in[0];
        coords = (const int*)d_in[1];
        perm = (const int*)d_in[2];
        inv_perm = (const int*)d_in[3];
        pos_w = (const float*)d_in[4];
        pos_b = (const float*)d_in[5];
        rms_w = (const float*)d_in[6];
        in_proj_w = (const float*)d_in[7];
        conv_w = (const float*)d_in[8];
        conv_b = (const float*)d_in[9];
        x_proj_w = (const float*)d_in[10];
        dt_w = (const float*)d_in[11];
        dt_b = (const float*)d_in[12];
        A_log = (const float*)d_in[13];
        Dskip = (const float*)d_in[14];
        out_proj_w = (const float*)d_in[15];
        ln_w = (const float*)d_in[16];
        ln_b = (const float*)d_in[17];
    } else {
        vf = (const float*)d_in[0];
        pos_w = (const float*)d_in[1];
        pos_b = (const float*)d_in[2];
        rms_w = (const float*)d_in[3];
        in_proj_w = (const float*)d_in[4];
        conv_w = (const float*)d_in[5];
        conv_b = (const float*)d_in[6];
        x_proj_w = (const float*)d_in[7];
        dt_w = (const float*)d_in[8];
        dt_b = (const float*)d_in[9];
        A_log = (const float*)d_in[10];
        Dskip = (const float*)d_in[11];
        out_proj_w = (const float*)d_in[12];
        ln_w = (const float*)d_in[13];
        ln_b = (const float*)d_in[14];
        coords = (const int*)d_in[15];
        perm = (const int*)d_in[16];
        inv_perm = (const int*)d_in[17];
    }
    (void)inv_perm;

    void *p_rmsb, *p_xzb, *p_xcb, *p_dbc, *p_yb, *p_resid, *p_w1b, *p_w2b, *p_w3b;
    cudaGetSymbolAddress(&p_rmsb, g_rmsb);
    cudaGetSymbolAddress(&p_xzb, g_xzb);
    cudaGetSymbolAddress(&p_xcb, g_xcb);
    cudaGetSymbolAddress(&p_dbc, g_dbc);
    cudaGetSymbolAddress(&p_yb, g_yb);
    cudaGetSymbolAddress(&p_resid, g_resid);
    cudaGetSymbolAddress(&p_w1b, g_w1b);
    cudaGetSymbolAddress(&p_w2b, g_w2b);
    cudaGetSymbolAddress(&p_w3b, g_w3b);

    k_wcvt<<<448, 256>>>(in_proj_w, x_proj_w, out_proj_w);
    k_pre<<<NN, 128>>>(vf, coords, perm, pos_w, pos_b, rms_w);
    bgemm<2, true><<<dim3(NN / 128, 512 / 64), 256>>>(
        (const __nv_bfloat16*)p_rmsb, (const __nv_bfloat16*)p_w1b, p_xzb, 512, 128);
    k_conv<<<(NN / 16), 256>>>(conv_w, conv_b);
    bgemm<1, false><<<dim3(NN / 64, 1), 256>>>(
        (const __nv_bfloat16*)p_xcb, (const __nv_bfloat16*)p_w2b, p_dbc, 64, 256);
    k_scan1<<<NCH, DIc>>>(A_log, dt_w, dt_b);
    k_combine<<<DIc * DSc / 256, 256>>>();
    k_scan2<<<NCH, DIc>>>(A_log, dt_w, dt_b, Dskip);
    k_outln<<<NN / 64, 256>>>((const __nv_bfloat16*)p_yb, (const __nv_bfloat16*)p_w3b,
                              (const float*)p_resid, perm, ln_w, ln_b, (float*)d_out);
    (void)n_in;
    (void)out_size;
    (void)in_sizes;
}

// round 17
// speedup vs baseline: 1.4752x; 1.0106x over previous
#include <cuda_runtime.h>
#include <cuda_bf16.h>
#include <cstdint>

#define NN 32768
#define DD 128
#define DIc 256
#define DSc 16
#define LC 128
#define NCH (NN / LC)
#define EPSF 1e-5f
#define LOG2E 1.4426950408889634f
#define LN2F 0.6931471805599453f

// ---------------- scratch (device globals; no allocation allowed) -------------
__device__ float g_resid[NN * DD];
__device__ __nv_bfloat16 g_rmsb[NN * DD];
__device__ __nv_bfloat16 g_xzb[NN * 2 * DIc];
__device__ __nv_bfloat16 g_xcb[NN * DIc];
__device__ float g_dbc[NN * 64];
__device__ float g_P[NCH * DIc * DSc];
__device__ float g_He[NCH * DIc * DSc];
__device__ float g_Hin[NCH * DIc * DSc];
__device__ __nv_bfloat16 g_yb[NN * DIc];
__device__ __nv_bfloat16 g_w1b[DD * 512];
__device__ __nv_bfloat16 g_w2b[DIc * 64];
__device__ __nv_bfloat16 g_w3b[DIc * DD];

// ---------------- helpers -----------------------------------------------------
__device__ __forceinline__ float ex2(float x) {
    float y;
    asm("ex2.approx.ftz.f32 %0, %1;" : "=f"(y) : "f"(x));
    return y;
}
__device__ __forceinline__ float lg2(float x) {
    float y;
    asm("lg2.approx.ftz.f32 %0, %1;" : "=f"(y) : "f"(x));
    return y;
}
__device__ __forceinline__ float fexp(float x) { return ex2(x * LOG2E); }
__device__ __forceinline__ float silu_f(float x) { return x / (1.0f + fexp(-x)); }
__device__ __forceinline__ float softplus_fast(float v) {
    float t = ex2(v * LOG2E);
    float r = LN2F * lg2(1.0f + t);
    return v > 20.0f ? v : r;
}
__device__ __forceinline__ void ldsm4(uint32_t& r0, uint32_t& r1, uint32_t& r2, uint32_t& r3,
                                      uint32_t a) {
    asm volatile("ldmatrix.sync.aligned.m8n8.x4.shared.b16 {%0,%1,%2,%3},[%4];"
                 : "=r"(r0), "=r"(r1), "=r"(r2), "=r"(r3)
                 : "r"(a));
}
__device__ __forceinline__ void ldsm4t(uint32_t& r0, uint32_t& r1, uint32_t& r2, uint32_t& r3,
                                       uint32_t a) {
    asm volatile("ldmatrix.sync.aligned.m8n8.x4.trans.shared.b16 {%0,%1,%2,%3},[%4];"
                 : "=r"(r0), "=r"(r1), "=r"(r2), "=r"(r3)
                 : "r"(a));
}
__device__ __forceinline__ void mma_bf16(float* c, const uint32_t* a, const uint32_t* b) {
    asm volatile(
        "mma.sync.aligned.m16n8k16.row.col.f32.bf16.bf16.f32 "
        "{%0,%1,%2,%3},{%4,%5,%6,%7},{%8,%9},{%0,%1,%2,%3};"
        : "+f"(c[0]), "+f"(c[1]), "+f"(c[2]), "+f"(c[3])
        : "r"(a[0]), "r"(a[1]), "r"(a[2]), "r"(a[3]), "r"(b[0]), "r"(b[1]));
}
__device__ __forceinline__ void cpa16(uint32_t s, const void* g) {
    asm volatile("cp.async.cg.shared.global [%0], [%1], 16;" ::"r"(s), "l"(g));
}
__device__ __forceinline__ void cp_commit() { asm volatile("cp.async.commit_group;"); }
template <int NG>
__device__ __forceinline__ void cp_wait() {
    asm volatile("cp.async.wait_group %0;" ::"n"(NG));
}
// r^(s+1) for s=0..15, log-depth (scalar — verified faster than f32x2 pairs on B300)
__device__ __forceinline__ void pow_chain(float r, float* a) {
    a[0] = r;
    a[1] = r * r;
    a[2] = a[1] * r;
    a[3] = a[1] * a[1];
    a[4] = a[3] * r;
    a[5] = a[2] * a[2];
    a[6] = a[5] * r;
    a[7] = a[3] * a[3];
    a[8] = a[7] * r;
    a[9] = a[4] * a[4];
    a[10] = a[9] * r;
    a[11] = a[5] * a[5];
    a[12] = a[11] * r;
    a[13] = a[6] * a[6];
    a[14] = a[13] * r;
    a[15] = a[7] * a[7];
}

// ---------------- kernel 0: convert weights to bf16 (+ pad x_proj) ------------
__global__ void k_wcvt(const float* __restrict__ w1, const float* __restrict__ xw,
                       const float* __restrict__ w3) {
    int idx = blockIdx.x * blockDim.x + threadIdx.x;
    if (idx < DD * 512) {
        g_w1b[idx] = __float2bfloat16(w1[idx]);
    } else if (idx < DD * 512 + DIc * 64) {
        int i = idx - DD * 512;
        int k = i >> 6, j = i & 63;
        g_w2b[i] = __float2bfloat16(j < 40 ? xw[k * 40 + j] : 0.0f);
    } else {
        int i = idx - DD * 512 - DIc * 64;
        g_w3b[i] = __float2bfloat16(w3[i]);
    }
}

// ---------------- kernel 1: pos-encode + gather(perm) + RMSNorm ---------------
__global__ void k_pre(const float* __restrict__ vf, const int* __restrict__ coords,
                      const int* __restrict__ perm, const float* __restrict__ pos_w,
                      const float* __restrict__ pos_b, const float* __restrict__ rms_w) {
    int i = blockIdx.x;
    int d = threadIdx.x;  // 128
    int j = perm[i];
    int cz = coords[j * 4 + 1];
    int cy = coords[j * 4 + 2];
    int cx = coords[j * 4 + 3];
    const float dnm = 1.0f / 43.0f;
    const float t12 = 1.0f / 12.0f;
    float pf[9];
    pf[0] = (float)cz * (1.0f / 16.0f);
    pf[1] = (float)(cy / 12) * dnm;
    pf[2] = (float)(cx / 12) * dnm;
    pf[3] = (float)(cy % 12) * t12;
    pf[4] = (float)(cx % 12) * t12;
    pf[5] = (float)((cy + 6) / 12) * dnm;
    pf[6] = (float)((cx + 6) / 12) * dnm;
    pf[7] = (float)((cy + 6) % 12) * t12;
    pf[8] = (float)((cx + 6) % 12) * t12;
    float pe = pos_b[d];
#pragma unroll
    for (int f = 0; f < 9; f++) pe = fmaf(pf[f], pos_w[f * DD + d], pe);
    float val = vf[(size_t)j * DD + d] + pe;
    g_resid[(size_t)i * DD + d] = val;

    float v2 = val * val;
#pragma unroll
    for (int o = 16; o > 0; o >>= 1) v2 += __shfl_xor_sync(0xffffffffu, v2, o);
    __shared__ float red[4];
    if ((d & 31) == 0) red[d >> 5] = v2;
    __syncthreads();
    float ms = (red[0] + red[1] + red[2] + red[3]) * (1.0f / 128.0f);
    g_rmsb[(size_t)i * DD + d] = __float2bfloat16(val * rsqrtf(ms + EPSF) * rms_w[d]);
}

// ---------------- bf16 TC GEMM, cp.async double-buffered (runtime Nc/Kd) ------
// colBase lets a launch cover a column sub-range (used to split in_proj x/z).
template <int MT, bool OUTB>
__global__ void bgemm(const __nv_bfloat16* __restrict__ A, const __nv_bfloat16* __restrict__ B,
                      void* __restrict__ Cout, int Nc, int Kd, int colBase) {
    constexpr int BM = MT * 64;
    constexpr int BK = 32;
    constexpr int LDA = 112;
    constexpr int LDB = 144;
    __shared__ __align__(16) unsigned char As[2][BM * LDA];
    __shared__ __align__(16) unsigned char Bs[2][BK * LDB];
    int tid = threadIdx.x;
    int lane = tid & 31;
    int warp = tid >> 5;
    int wr = warp & 3;
    int wc = warp >> 2;
    long row0 = (long)blockIdx.x * BM;
    int col0 = colBase + blockIdx.y * 64;

    float acc[MT][4][4];
#pragma unroll
    for (int m = 0; m < MT; m++)
#pragma unroll
        for (int n = 0; n < 4; n++)
#pragma unroll
            for (int r = 0; r < 4; r++) acc[m][n][r] = 0.0f;

    uint32_t asb[2], bsb[2];
    asb[0] = (uint32_t)__cvta_generic_to_shared(&As[0][0]);
    asb[1] = (uint32_t)__cvta_generic_to_shared(&As[1][0]);
    bsb[0] = (uint32_t)__cvta_generic_to_shared(&Bs[0][0]);
    bsb[1] = (uint32_t)__cvta_generic_to_shared(&Bs[1][0]);

    int ar = tid >> 2, ac = tid & 3;
    int br = tid >> 3, bc = tid & 7;

    auto issue = [&](int buf, int k0) {
#pragma unroll
        for (int it = 0; it < MT; it++) {
            int r = ar + it * 64;
            cpa16(asb[buf] + r * LDA + ac * 16, A + (row0 + r) * Kd + k0 + ac * 8);
        }
        cpa16(bsb[buf] + br * LDB + bc * 16, B + (long)(k0 + br) * Nc + col0 + bc * 8);
        cp_commit();
    };

    int KT = Kd / BK;
    issue(0, 0);
    int buf = 0;

    int a_row_in_tile = lane & 15;
    int a_colh = (lane >> 4) << 3;
    int b_krow = (lane & 7) + (((lane >> 3) & 1) << 3);
    int b_ncol = (lane >> 4) << 3;

    for (int kt = 0; kt < KT; kt++) {
        if (kt + 1 < KT) {
            issue(buf ^ 1, (kt + 1) * BK);
            cp_wait<1>();
        } else {
            cp_wait<0>();
        }
        __syncthreads();
#pragma unroll
        for (int ks = 0; ks < 2; ks++) {
            int kh = ks * 16;
            uint32_t a[MT][4];
#pragma unroll
            for (int mt = 0; mt < MT; mt++) {
                int row = wr * (MT * 16) + mt * 16 + a_row_in_tile;
                ldsm4(a[mt][0], a[mt][1], a[mt][2], a[mt][3],
                      asb[buf] + row * LDA + (kh + a_colh) * 2);
            }
            uint32_t b[4][2];
#pragma unroll
            for (int np = 0; np < 2; np++) {
                int krow = kh + b_krow;
                int ncol = wc * 32 + np * 16 + b_ncol;
                uint32_t r0, r1, r2, r3;
                ldsm4t(r0, r1, r2, r3, bsb[buf] + krow * LDB + ncol * 2);
                b[np * 2][0] = r0;
                b[np * 2][1] = r1;
                b[np * 2 + 1][0] = r2;
                b[np * 2 + 1][1] = r3;
            }
#pragma unroll
            for (int mt = 0; mt < MT; mt++)
#pragma unroll
                for (int nt = 0; nt < 4; nt++) mma_bf16(acc[mt][nt], a[mt], b[nt]);
        }
        __syncthreads();
        buf ^= 1;
    }

    int g = lane >> 2;
    int tg = lane & 3;
#pragma unroll
    for (int mt = 0; mt < MT; mt++) {
#pragma unroll
        for (int nt = 0; nt < 4; nt++) {
            long r0 = row0 + wr * (MT * 16) + mt * 16 + g;
            int c = col0 + wc * 32 + nt * 8 + tg * 2;
            if (OUTB) {
                __nv_bfloat16* C = (__nv_bfloat16*)Cout;
                *(__nv_bfloat162*)(C + r0 * Nc + c) =
                    __float22bfloat162_rn(make_float2(acc[mt][nt][0], acc[mt][nt][1]));
                *(__nv_bfloat162*)(C + (r0 + 8) * Nc + c) =
                    __float22bfloat162_rn(make_float2(acc[mt][nt][2], acc[mt][nt][3]));
            } else {
                float* C = (float*)Cout;
                *(float2*)(C + r0 * Nc + c) = make_float2(acc[mt][nt][0], acc[mt][nt][1]);
                *(float2*)(C + (r0 + 8) * Nc + c) = make_float2(acc[mt][nt][2], acc[mt][nt][3]);
            }
        }
    }
}

// ---------------- kernel 3: causal conv — 2 channels/thread, bf16x2 I/O -------
__global__ void k_conv(const float* __restrict__ conv_w, const float* __restrict__ conv_b) {
    int idx = blockIdx.x * blockDim.x + threadIdx.x;  // (NN/8)*128
    int tb = idx >> 7;
    int cp = idx & 127;
    int c = cp * 2;
    int t0 = tb * 8;
    float4 wA = *(const float4*)(conv_w + c * 4);
    float4 wB = *(const float4*)(conv_w + c * 4 + 4);
    float2 bias = *(const float2*)(conv_b + c);
    float2 v[11];
#pragma unroll
    for (int i = 0; i < 11; i++) {
        int t = t0 - 3 + i;
        if (t >= 0) {
            __nv_bfloat162 h = *(const __nv_bfloat162*)(g_xzb + (size_t)t * 512 + c);
            v[i] = __bfloat1622float2(h);
        } else {
            v[i] = make_float2(0.0f, 0.0f);
        }
    }
#pragma unroll
    for (int j = 0; j < 8; j++) {
        float sa = bias.x, sb = bias.y;
        sa = fmaf(wA.x, v[j].x, sa);
        sb = fmaf(wB.x, v[j].y, sb);
        sa = fmaf(wA.y, v[j + 1].x, sa);
        sb = fmaf(wB.y, v[j + 1].y, sb);
        sa = fmaf(wA.z, v[j + 2].x, sa);
        sb = fmaf(wB.z, v[j + 2].y, sb);
        sa = fmaf(wA.w, v[j + 3].x, sa);
        sb = fmaf(wB.w, v[j + 3].y, sb);
        *(__nv_bfloat162*)(g_xcb + (size_t)(t0 + j) * DIc + c) =
            __float22bfloat162_rn(make_float2(silu_f(sa), silu_f(sb)));
    }
}

// ---------------- kernel 7: scan pass 1 (inline dt; scalar; LC=128) -----------
__global__ void k_scan1(const float* __restrict__ A_log, const float* __restrict__ dtw,
                        const float* __restrict__ dtb) {
    int chunk = blockIdx.x;
    int c = threadIdx.x;
    __shared__ float U[LC][8];
    __shared__ float Bsh[LC][16];
    int t0 = chunk * LC;
    {
        int row = threadIdx.x >> 1, q = threadIdx.x & 1;
        *(float4*)&U[row][q * 4] = *(const float4*)(g_dbc + (size_t)(t0 + row) * 64 + q * 4);
#pragma unroll
        for (int it = 0; it < 2; it++) {
            int v = threadIdx.x + it * 256;
            int r2 = v >> 2, q2 = v & 3;
            *(float4*)&Bsh[r2][q2 * 4] =
                *(const float4*)(g_dbc + (size_t)(t0 + r2) * 64 + 8 + q2 * 4);
        }
    }
    __syncthreads();
    float w8[8];
#pragma unroll
    for (int k = 0; k < 8; k++) w8[k] = dtw[k * DIc + c];
    float b0 = dtb[c];
    float A2[DSc];
#pragma unroll
    for (int s = 0; s < DSc; s++) A2[s] = -__expf(A_log[c * DSc + s]) * LOG2E;
    float base = A2[0];
    bool structured = true;
#pragma unroll
    for (int s = 0; s < DSc; s++) {
        float e = base * (float)(s + 1);
        structured = structured && (fabsf(A2[s] - e) <= 1e-5f * fabsf(e) + 1e-30f);
    }
    float h[DSc];
#pragma unroll
    for (int s = 0; s < DSc; s++) h[s] = 0.0f;
    float sdt = 0.0f;
    if (structured) {
#pragma unroll 2
        for (int t = 0; t < LC; t++) {
            float dot = b0;
#pragma unroll
            for (int k = 0; k < 8; k++) dot = fmaf(w8[k], U[t][k], dot);
            float d = softplus_fast(dot);
            float x = __bfloat162float(g_xcb[(size_t)(t0 + t) * DIc + c]);
            float dx = d * x;
            sdt += d;
            float a[DSc];
            pow_chain(ex2(d * base), a);
#pragma unroll
            for (int s = 0; s < DSc; s++) h[s] = fmaf(a[s], h[s], dx * Bsh[t][s]);
        }
    } else {
#pragma unroll 2
        for (int t = 0; t < LC; t++) {
            float dot = b0;
#pragma unroll
            for (int k = 0; k < 8; k++) dot = fmaf(w8[k], U[t][k], dot);
            float d = softplus_fast(dot);
            float x = __bfloat162float(g_xcb[(size_t)(t0 + t) * DIc + c]);
            float dx = d * x;
            sdt += d;
#pragma unroll
            for (int s = 0; s < DSc; s++) {
                float a = ex2(d * A2[s]);
                h[s] = fmaf(a, h[s], dx * Bsh[t][s]);
            }
        }
    }
    size_t o = ((size_t)chunk * DIc + c) * DSc;
#pragma unroll
    for (int s = 0; s < DSc; s++) {
        g_He[o + s] = h[s];
        g_P[o + s] = ex2(sdt * A2[s]);
    }
}

// ---------------- kernel 8: cross-chunk combine -------------------------------
__global__ void k_combine() {
    int idx = blockIdx.x * blockDim.x + threadIdx.x;
    float h = 0.0f;
    for (int k = 0; k < NCH; k++) {
        size_t o = (size_t)k * DIc * DSc + idx;
        g_Hin[o] = h;
        h = fmaf(g_P[o], h, g_He[o]);
    }
}

// ---------------- kernel 9: scan pass 2 (inline dt; scalar; LC=128) -----------
__global__ void k_scan2(const float* __restrict__ A_log, const float* __restrict__ dtw,
                        const float* __restrict__ dtb, const float* __restrict__ Dskip) {
    int chunk = blockIdx.x;
    int c = threadIdx.x;
    __shared__ float U[LC][8];
    __shared__ float Bsh[LC][16];
    __shared__ float Csh[LC][16];
    int t0 = chunk * LC;
    {
        int row = threadIdx.x >> 1, q = threadIdx.x & 1;
        *(float4*)&U[row][q * 4] = *(const float4*)(g_dbc + (size_t)(t0 + row) * 64 + q * 4);
#pragma unroll
        for (int it = 0; it < 2; it++) {
            int v = threadIdx.x + it * 256;
            int r2 = v >> 2, q2 = v & 3;
            *(float4*)&Bsh[r2][q2 * 4] =
                *(const float4*)(g_dbc + (size_t)(t0 + r2) * 64 + 8 + q2 * 4);
            *(float4*)&Csh[r2][q2 * 4] =
                *(const float4*)(g_dbc + (size_t)(t0 + r2) * 64 + 24 + q2 * 4);
        }
    }
    __syncthreads();
    float w8[8];
#pragma unroll
    for (int k = 0; k < 8; k++) w8[k] = dtw[k * DIc + c];
    float b0 = dtb[c];
    float A2[DSc];
#pragma unroll
    for (int s = 0; s < DSc; s++) A2[s] = -__expf(A_log[c * DSc + s]) * LOG2E;
    float base = A2[0];
    bool structured = true;
#pragma unroll
    for (int s = 0; s < DSc; s++) {
        float e = base * (float)(s + 1);
        structured = structured && (fabsf(A2[s] - e) <= 1e-5f * fabsf(e) + 1e-30f);
    }
    float h[DSc];
    size_t oh = ((size_t)chunk * DIc + c) * DSc;
#pragma unroll
    for (int s = 0; s < DSc; s++) h[s] = g_Hin[oh + s];
    float dsk = Dskip[c];
    if (structured) {
#pragma unroll 2
        for (int t = 0; t < LC; t++) {
            float dot = b0;
#pragma unroll
            for (int k = 0; k < 8; k++) dot = fmaf(w8[k], U[t][k], dot);
            float d = softplus_fast(dot);
            float x = __bfloat162float(g_xcb[(size_t)(t0 + t) * DIc + c]);
            float z = __bfloat162float(g_xzb[(size_t)(t0 + t) * 512 + DIc + c]);
            float dx = d * x;
            float a[DSc];
            pow_chain(ex2(d * base), a);
            float acc = 0.0f;
#pragma unroll
            for (int s = 0; s < DSc; s++) {
                h[s] = fmaf(a[s], h[s], dx * Bsh[t][s]);
                acc = fmaf(h[s], Csh[t][s], acc);
            }
            acc = fmaf(dsk, x, acc);
            g_yb[(size_t)(t0 + t) * DIc + c] = __float2bfloat16(acc * silu_f(z));
        }
    } else {
#pragma unroll 2
        for (int t = 0; t < LC; t++) {
            float dot = b0;
#pragma unroll
            for (int k = 0; k < 8; k++) dot = fmaf(w8[k], U[t][k], dot);
            float d = softplus_fast(dot);
            float x = __bfloat162float(g_xcb[(size_t)(t0 + t) * DIc + c]);
            float z = __bfloat162float(g_xzb[(size_t)(t0 + t) * 512 + DIc + c]);
            float dx = d * x;
            float acc = 0.0f;
#pragma unroll
            for (int s = 0; s < DSc; s++) {
                float a = ex2(d * A2[s]);
                h[s] = fmaf(a, h[s], dx * Bsh[t][s]);
                acc = fmaf(h[s], Csh[t][s], acc);
            }
            acc = fmaf(dsk, x, acc);
            g_yb[(size_t)(t0 + t) * DIc + c] = __float2bfloat16(acc * silu_f(z));
        }
    }
}

// ---------------- kernel 10: fused out_proj + residual + LN + scatter ---------
__global__ void k_outln(const __nv_bfloat16* __restrict__ A, const __nv_bfloat16* __restrict__ B,
                        const float* __restrict__ resid, const int* __restrict__ perm,
                        const float* __restrict__ ln_w, const float* __restrict__ ln_b,
                        float* __restrict__ out) {
    constexpr int BK = 32, Kd = 256, Nc = 128;
    constexpr int LDA = 112;
    constexpr int LDB = 272;
    __shared__ __align__(16) unsigned char As[2][64 * LDA];
    __shared__ __align__(16) unsigned char Bs[2][BK * LDB];
    __shared__ float redA[64][2], redB[64][2];
    int tid = threadIdx.x;
    int lane = tid & 31;
    int warp = tid >> 5;
    int wr = warp & 3;
    int wc = warp >> 2;
    long row0 = (long)blockIdx.x * 64;

    float acc[8][4];
#pragma unroll
    for (int n = 0; n < 8; n++)
#pragma unroll
        for (int r = 0; r < 4; r++) acc[n][r] = 0.0f;

    uint32_t asb[2], bsb[2];
    asb[0] = (uint32_t)__cvta_generic_to_shared(&As[0][0]);
    asb[1] = (uint32_t)__cvta_generic_to_shared(&As[1][0]);
    bsb[0] = (uint32_t)__cvta_generic_to_shared(&Bs[0][0]);
    bsb[1] = (uint32_t)__cvta_generic_to_shared(&Bs[1][0]);

    int ar = tid >> 2, ac = tid & 3;
    int br = tid >> 3, bc = tid & 7;

    auto issue = [&](int buf, int k0) {
        cpa16(asb[buf] + ar * LDA + ac * 16, A + (row0 + ar) * Kd + k0 + ac * 8);
        cpa16(bsb[buf] + br * LDB + bc * 16, B + (long)(k0 + br) * Nc + bc * 8);
        cpa16(bsb[buf] + br * LDB + 128 + bc * 16, B + (long)(k0 + br) * Nc + 64 + bc * 8);
        cp_commit();
    };

    issue(0, 0);
    int buf = 0;
    int a_row_in_tile = lane & 15;
    int a_colh = (lane >> 4) << 3;
    int b_krow = (lane & 7) + (((lane >> 3) & 1) << 3);
    int b_ncol = (lane >> 4) << 3;

    constexpr int KT = Kd / BK;
    for (int kt = 0; kt < KT; kt++) {
        if (kt + 1 < KT) {
            issue(buf ^ 1, (kt + 1) * BK);
            cp_wait<1>();
        } else {
            cp_wait<0>();
        }
        __syncthreads();
#pragma unroll
        for (int ks = 0; ks < 2; ks++) {
            int kh = ks * 16;
            uint32_t a[4];
            {
                int row = wr * 16 + a_row_in_tile;
                ldsm4(a[0], a[1], a[2], a[3], asb[buf] + row * LDA + (kh + a_colh) * 2);
            }
            uint32_t b[8][2];
#pragma unroll
            for (int np = 0; np < 4; np++) {
                int krow = kh + b_krow;
                int ncol = wc * 64 + np * 16 + b_ncol;
                uint32_t r0, r1, r2, r3;
                ldsm4t(r0, r1, r2, r3, bsb[buf] + krow * LDB + ncol * 2);
                b[np * 2][0] = r0;
                b[np * 2][1] = r1;
                b[np * 2 + 1][0] = r2;
                b[np * 2 + 1][1] = r3;
            }
#pragma unroll
            for (int nt = 0; nt < 8; nt++) mma_bf16(acc[nt], a, b[nt]);
        }
        __syncthreads();
        buf ^= 1;
    }

    int g = lane >> 2;
    int tg = lane & 3;
    int rA = wr * 16 + g;
    int rB = rA + 8;
    float va[16], vb[16];
    float s1a = 0.f, s2a = 0.f, s1b = 0.f, s2b = 0.f;
#pragma unroll
    for (int nt = 0; nt < 8; nt++) {
        int cc = wc * 64 + nt * 8 + tg * 2;
        float2 sa = *(const float2*)(resid + (row0 + rA) * Nc + cc);
        float2 sb = *(const float2*)(resid + (row0 + rB) * Nc + cc);
        float x0 = acc[nt][0] + sa.x, x1 = acc[nt][1] + sa.y;
        float x2 = acc[nt][2] + sb.x, x3 = acc[nt][3] + sb.y;
        va[nt * 2] = x0; va[nt * 2 + 1] = x1;
        vb[nt * 2] = x2; vb[nt * 2 + 1] = x3;
        s1a += x0 + x1; s2a += x0 * x0 + x1 * x1;
        s1b += x2 + x3; s2b += x2 * x2 + x3 * x3;
    }
#pragma unroll
    for (int o = 1; o <= 2; o <<= 1) {
        s1a += __shfl_xor_sync(0xffffffffu, s1a, o);
        s2a += __shfl_xor_sync(0xffffffffu, s2a, o);
        s1b += __shfl_xor_sync(0xffffffffu, s1b, o);
        s2b += __shfl_xor_sync(0xffffffffu, s2b, o);
    }
    if (tg == 0) {
        redA[rA][wc] = s1a; redB[rA][wc] = s2a;
        redA[rB][wc] = s1b; redB[rB][wc] = s2b;
    }
    __syncthreads();
    float muA = (redA[rA][0] + redA[rA][1]) * (1.0f / 128.0f);
    float e2A = (redB[rA][0] + redB[rA][1]) * (1.0f / 128.0f);
    float muB = (redA[rB][0] + redA[rB][1]) * (1.0f / 128.0f);
    float e2B = (redB[rB][0] + redB[rB][1]) * (1.0f / 128.0f);
    float rsA = rsqrtf(e2A - muA * muA + EPSF);
    float rsB = rsqrtf(e2B - muB * muB + EPSF);
    int prA = perm[row0 + rA];
    int prB = perm[row0 + rB];
#pragma unroll
    for (int nt = 0; nt < 8; nt++) {
        int cc = wc * 64 + nt * 8 + tg * 2;
        float2 w = *(const float2*)(ln_w + cc);
        float2 bb = *(const float2*)(ln_b + cc);
        float2 oa, ob;
        oa.x = (va[nt * 2] - muA) * rsA * w.x + bb.x;
        oa.y = (va[nt * 2 + 1] - muA) * rsA * w.y + bb.y;
        ob.x = (vb[nt * 2] - muB) * rsB * w.x + bb.x;
        ob.y = (vb[nt * 2 + 1] - muB) * rsB * w.y + bb.y;
        *(float2*)(out + (size_t)prA * Nc + cc) = oa;
        *(float2*)(out + (size_t)prB * Nc + cc) = ob;
    }
}

// ---------------- host ---------------------------------------------------------
extern "C" void kernel_launch(void* const* d_in, const int* in_sizes, int n_in,
                              void* d_out, int out_size) {
    const float *vf, *pos_w, *pos_b, *rms_w, *in_proj_w, *conv_w, *conv_b, *x_proj_w;
    const float *dt_w, *dt_b, *A_log, *Dskip, *out_proj_w, *ln_w, *ln_b;
    const int *coords, *perm, *inv_perm;

    if (in_sizes[1] == NN * 4) {
        vf = (const float*)d_in[0];
        coords = (const int*)d_in[1];
        perm = (const int*)d_in[2];
        inv_perm = (const int*)d_in[3];
        pos_w = (const float*)d_in[4];
        pos_b = (const float*)d_in[5];
        rms_w = (const float*)d_in[6];
        in_proj_w = (const float*)d_in[7];
        conv_w = (const float*)d_in[8];
        conv_b = (const float*)d_in[9];
        x_proj_w = (const float*)d_in[10];
        dt_w = (const float*)d_in[11];
        dt_b = (const float*)d_in[12];
        A_log = (const float*)d_in[13];
        Dskip = (const float*)d_in[14];
        out_proj_w = (const float*)d_in[15];
        ln_w = (const float*)d_in[16];
        ln_b = (const float*)d_in[17];
    } else {
        vf = (const float*)d_in[0];
        pos_w = (const float*)d_in[1];
        pos_b = (const float*)d_in[2];
        rms_w = (const float*)d_in[3];
        in_proj_w = (const float*)d_in[4];
        conv_w = (const float*)d_in[5];
        conv_b = (const float*)d_in[6];
        x_proj_w = (const float*)d_in[7];
        dt_w = (const float*)d_in[8];
        dt_b = (const float*)d_in[9];
        A_log = (const float*)d_in[10];
        Dskip = (const float*)d_in[11];
        out_proj_w = (const float*)d_in[12];
        ln_w = (const float*)d_in[13];
        ln_b = (const float*)d_in[14];
        coords = (const int*)d_in[15];
        perm = (const int*)d_in[16];
        inv_perm = (const int*)d_in[17];
    }
    (void)inv_perm;

    void *p_rmsb, *p_xzb, *p_xcb, *p_dbc, *p_yb, *p_resid, *p_w1b, *p_w2b, *p_w3b;
    cudaGetSymbolAddress(&p_rmsb, g_rmsb);
    cudaGetSymbolAddress(&p_xzb, g_xzb);
    cudaGetSymbolAddress(&p_xcb, g_xcb);
    cudaGetSymbolAddress(&p_dbc, g_dbc);
    cudaGetSymbolAddress(&p_yb, g_yb);
    cudaGetSymbolAddress(&p_resid, g_resid);
    cudaGetSymbolAddress(&p_w1b, g_w1b);
    cudaGetSymbolAddress(&p_w2b, g_w2b);
    cudaGetSymbolAddress(&p_w3b, g_w3b);

    // side stream + fork/join events (created per call; kernel_launch is only
    // invoked a handful of times — correctness + capture — so no cleanup needed)
    cudaStream_t s1;
    cudaStreamCreateWithFlags(&s1, cudaStreamNonBlocking);
    cudaEvent_t eFork, eJoin;
    cudaEventCreateWithFlags(&eFork, cudaEventDisableTiming);
    cudaEventCreateWithFlags(&eJoin, cudaEventDisableTiming);

    k_wcvt<<<448, 256>>>(in_proj_w, x_proj_w, out_proj_w);
    k_pre<<<NN, 128>>>(vf, coords, perm, pos_w, pos_b, rms_w);

    // fork: z-half of in_proj (cols 256..511, feeds only scan2) on side stream
    cudaEventRecord(eFork, 0);
    cudaStreamWaitEvent(s1, eFork, 0);
    bgemm<2, true><<<dim3(NN / 128, 4), 256, 0, s1>>>(
        (const __nv_bfloat16*)p_rmsb, (const __nv_bfloat16*)p_w1b, p_xzb, 512, 128, 256);
    cudaEventRecord(eJoin, s1);

    // main chain: x-half of in_proj (cols 0..255) -> conv -> x_proj -> scan1 -> combine
    bgemm<2, true><<<dim3(NN / 128, 4), 256>>>(
        (const __nv_bfloat16*)p_rmsb, (const __nv_bfloat16*)p_w1b, p_xzb, 512, 128, 0);
    k_conv<<<(NN / 16), 256>>>(conv_w, conv_b);
    bgemm<1, false><<<dim3(NN / 64, 1), 256>>>(
        (const __nv_bfloat16*)p_xcb, (const __nv_bfloat16*)p_w2b, p_dbc, 64, 256, 0);
    k_scan1<<<NCH, DIc>>>(A_log, dt_w, dt_b);
    k_combine<<<DIc * DSc / 256, 256>>>();

    // join: scan2 needs the z-half
    cudaStreamWaitEvent(0, eJoin, 0);
    k_scan2<<<NCH, DIc>>>(A_log, dt_w, dt_b, Dskip);
    k_outln<<<NN / 64, 256>>>((const __nv_bfloat16*)p_yb, (const __nv_bfloat16*)p_w3b,
                              (const float*)p_resid, perm, ln_w, ln_b, (float*)d_out);
    (void)n_in;
    (void)out_size;
    (void)in_sizes;
}